// round 12
// baseline (speedup 1.0000x reference)
#include <cuda_runtime.h>
#include <cuda_bf16.h>
#include <cstdint>

#define NODES 8192
#define H_ 128
#define K_ 48
#define EDGES (NODES * K_)
#define WTILES (EDGES / 16)
#define PAIRS (WTILES / 2)
#define NTILES (NODES / 16)
#define HV_ELEMS (NODES * H_)
#define LDW 136

__device__ __align__(16) float         g_v1[NODES * H_];
__device__ __align__(16) __nv_bfloat16 g_fb[NODES * 512];
__device__ __align__(16) __nv_bfloat16 g_hvb[NODES * H_];
__device__ __align__(16) float         g_dh[NODES * H_];
__device__ __align__(16) float         g_biasA[NODES * H_];
__device__ __align__(16) float         g_biasC[NODES * H_];

static __device__ __forceinline__ unsigned su32(const void* p) {
    return (unsigned)__cvta_generic_to_shared(p);
}
static __device__ __forceinline__ float gelu_f(float x) {
    float u = 0.7978845608028654f * (x + 0.044715f * x * x * x), t;
    asm("tanh.approx.f32 %0, %1;" : "=f"(t) : "f"(u));
    return 0.5f * x * (1.0f + t);
}
static __device__ __forceinline__ uint32_t pk(float x, float y) {
    __nv_bfloat162 h = __floats2bfloat162_rn(x, y);
    return *(uint32_t*)&h;
}
static __device__ __forceinline__ void load_w(const float* g, __nv_bfloat16* s,
                                              int rows, int tid, int nthr) {
    int total4 = rows * 32;
    for (int i = tid; i < total4; i += nthr) {
        float4 w = ((const float4*)g)[i];
        int r = (i * 4) >> 7, c = (i * 4) & 127;
        *(__nv_bfloat162*)(s + r * LDW + c)     = __floats2bfloat162_rn(w.x, w.y);
        *(__nv_bfloat162*)(s + r * LDW + c + 2) = __floats2bfloat162_rn(w.z, w.w);
    }
}

#define MMA4(ac, a, b0, b1) \
    asm volatile("mma.sync.aligned.m16n8k16.row.col.f32.bf16.bf16.f32 " \
                 "{%0,%1,%2,%3},{%4,%5,%6,%7},{%8,%9},{%0,%1,%2,%3};" \
                 : "+f"((ac)[0]), "+f"((ac)[1]), "+f"((ac)[2]), "+f"((ac)[3]) \
                 : "r"((a)[0]), "r"((a)[1]), "r"((a)[2]), "r"((a)[3]), \
                   "r"(b0), "r"(b1))

static __device__ __forceinline__ void zero16(float acc[16][4]) {
    #pragma unroll
    for (int i = 0; i < 16; ++i)
        #pragma unroll
        for (int j = 0; j < 4; ++j) acc[i][j] = 0.0f;
}

template <int NKT>
static __device__ __forceinline__ void gemm_reg(const uint32_t* af, uint32_t wAddr,
                                                float acc[16][4]) {
    #pragma unroll
    for (int kt = 0; kt < NKT; ++kt) {
        #pragma unroll
        for (int nb = 0; nb < 8; ++nb) {
            uint32_t b[4];
            asm volatile("ldmatrix.sync.aligned.m8n8.x4.trans.shared.b16 {%0,%1,%2,%3},[%4];"
                         : "=r"(b[0]), "=r"(b[1]), "=r"(b[2]), "=r"(b[3])
                         : "r"(wAddr + kt * 4352 + nb * 32));
            MMA4(acc[2 * nb],     af + 4 * kt, b[0], b[1]);
            MMA4(acc[2 * nb + 1], af + 4 * kt, b[2], b[3]);
        }
    }
}

// Dual-tile GEMM: b fragments loaded ONCE, feed both tiles' accumulators (4 HMMA / LDSM)
template <int NKT>
static __device__ __forceinline__ void gemm2(const uint32_t* afA, const uint32_t* afB,
                                             uint32_t wAddr,
                                             float accA[16][4], float accB[16][4]) {
    #pragma unroll
    for (int kt = 0; kt < NKT; ++kt) {
        #pragma unroll
        for (int nb = 0; nb < 8; ++nb) {
            uint32_t b[4];
            asm volatile("ldmatrix.sync.aligned.m8n8.x4.trans.shared.b16 {%0,%1,%2,%3},[%4];"
                         : "=r"(b[0]), "=r"(b[1]), "=r"(b[2]), "=r"(b[3])
                         : "r"(wAddr + kt * 4352 + nb * 32));
            MMA4(accA[2 * nb],     afA + 4 * kt, b[0], b[1]);
            MMA4(accA[2 * nb + 1], afA + 4 * kt, b[2], b[3]);
            MMA4(accB[2 * nb],     afB + 4 * kt, b[0], b[1]);
            MMA4(accB[2 * nb + 1], afB + 4 * kt, b[2], b[3]);
        }
    }
}

static __device__ __forceinline__ void load_af_f32(const float* r0, const float* r1,
                                                   int tg, uint32_t af[32]) {
    #pragma unroll
    for (int kt = 0; kt < 8; ++kt) {
        int c = kt * 16 + 2 * tg;
        float2 v0 = *(const float2*)(r0 + c);
        float2 v1 = *(const float2*)(r1 + c);
        float2 v2 = *(const float2*)(r0 + c + 8);
        float2 v3 = *(const float2*)(r1 + c + 8);
        af[4 * kt]     = pk(v0.x, v0.y);
        af[4 * kt + 1] = pk(v1.x, v1.y);
        af[4 * kt + 2] = pk(v2.x, v2.y);
        af[4 * kt + 3] = pk(v3.x, v3.y);
    }
}
static __device__ __forceinline__ void load_af_bf16(const __nv_bfloat16* r0,
                                                    const __nv_bfloat16* r1,
                                                    int tg, uint32_t af[32]) {
    #pragma unroll
    for (int kt = 0; kt < 8; ++kt) {
        int c = kt * 16 + 2 * tg;
        af[4 * kt]     = *(const uint32_t*)(r0 + c);
        af[4 * kt + 1] = *(const uint32_t*)(r1 + c);
        af[4 * kt + 2] = *(const uint32_t*)(r0 + c + 8);
        af[4 * kt + 3] = *(const uint32_t*)(r1 + c + 8);
    }
}
static __device__ __forceinline__ void pack_gelu(const float acc[16][4],
                                                 const float* bias, int tg,
                                                 uint32_t af[32]) {
    #pragma unroll
    for (int kt = 0; kt < 8; ++kt) {
        int n0 = 2 * kt, n1 = 2 * kt + 1;
        float2 bA = *(const float2*)(bias + n0 * 8 + 2 * tg);
        float2 bB = *(const float2*)(bias + n1 * 8 + 2 * tg);
        af[4 * kt]     = pk(gelu_f(acc[n0][0] + bA.x), gelu_f(acc[n0][1] + bA.y));
        af[4 * kt + 1] = pk(gelu_f(acc[n0][2] + bA.x), gelu_f(acc[n0][3] + bA.y));
        af[4 * kt + 2] = pk(gelu_f(acc[n1][0] + bB.x), gelu_f(acc[n1][1] + bB.y));
        af[4 * kt + 3] = pk(gelu_f(acc[n1][2] + bB.x), gelu_f(acc[n1][3] + bB.y));
    }
}

// epilogue mode0: masked sum over the 16 rows of one tile -> atomics into g_dh[node]
static __device__ __forceinline__ void epi0(float acc[16][4], const float* matt,
                                            int r0, int r1, int node,
                                            const float* b3s, int lane, int tg) {
    float m0 = __ldg(matt + r0), m1 = __ldg(matt + r1);
    #pragma unroll
    for (int nt = 0; nt < 16; ++nt) {
        float2 b = *(const float2*)(b3s + nt * 8 + 2 * tg);
        acc[nt][0] = (acc[nt][0] + b.x) * m0 + (acc[nt][2] + b.x) * m1;
        acc[nt][1] = (acc[nt][1] + b.y) * m0 + (acc[nt][3] + b.y) * m1;
    }
    #pragma unroll
    for (int o = 4; o < 32; o <<= 1)
        #pragma unroll
        for (int nt = 0; nt < 16; ++nt) {
            acc[nt][0] += __shfl_xor_sync(~0u, acc[nt][0], o);
            acc[nt][1] += __shfl_xor_sync(~0u, acc[nt][1], o);
        }
    if (lane < 4) {
        float* dst = g_dh + (size_t)node * 128;
        #pragma unroll
        for (int nt = 0; nt < 16; ++nt) {
            atomicAdd(dst + nt * 8 + 2 * lane,     acc[nt][0]);
            atomicAdd(dst + nt * 8 + 2 * lane + 1, acc[nt][1]);
        }
    }
}

// epilogue mode1: LN3(hE + msg) -> outE, per tile
static __device__ __forceinline__ void epi1(float acc[16][4], const float* hE,
                                            float* outE, int r0, int r1,
                                            const float* b3s, const float* g3,
                                            const float* bb3, int tg) {
    const float* e0 = hE + (size_t)r0 * 128;
    const float* e1 = hE + (size_t)r1 * 128;
    float sum0 = 0.f, sq0 = 0.f, sum1 = 0.f, sq1 = 0.f;
    #pragma unroll
    for (int nt = 0; nt < 16; ++nt) {
        int c = nt * 8 + 2 * tg;
        float2 b  = *(const float2*)(b3s + c);
        float2 h0 = *(const float2*)(e0 + c);
        float2 h1 = *(const float2*)(e1 + c);
        acc[nt][0] += b.x + h0.x; acc[nt][1] += b.y + h0.y;
        acc[nt][2] += b.x + h1.x; acc[nt][3] += b.y + h1.y;
        sum0 += acc[nt][0] + acc[nt][1];
        sq0  += acc[nt][0] * acc[nt][0] + acc[nt][1] * acc[nt][1];
        sum1 += acc[nt][2] + acc[nt][3];
        sq1  += acc[nt][2] * acc[nt][2] + acc[nt][3] * acc[nt][3];
    }
    #pragma unroll
    for (int o = 1; o < 4; o <<= 1) {
        sum0 += __shfl_xor_sync(~0u, sum0, o);
        sq0  += __shfl_xor_sync(~0u, sq0, o);
        sum1 += __shfl_xor_sync(~0u, sum1, o);
        sq1  += __shfl_xor_sync(~0u, sq1, o);
    }
    float mu0 = sum0 * (1.0f / 128.0f);
    float iv0 = rsqrtf(sq0 * (1.0f / 128.0f) - mu0 * mu0 + 1e-5f);
    float mu1 = sum1 * (1.0f / 128.0f);
    float iv1 = rsqrtf(sq1 * (1.0f / 128.0f) - mu1 * mu1 + 1e-5f);
    float* o0 = outE + (size_t)r0 * 128;
    float* o1 = outE + (size_t)r1 * 128;
    #pragma unroll
    for (int nt = 0; nt < 16; ++nt) {
        int c = nt * 8 + 2 * tg;
        float gx = __ldg(g3 + c), gy = __ldg(g3 + c + 1);
        float bx = __ldg(bb3 + c), by = __ldg(bb3 + c + 1);
        *(float2*)(o0 + c) = make_float2((acc[nt][0] - mu0) * iv0 * gx + bx,
                                         (acc[nt][1] - mu0) * iv0 * gy + by);
        *(float2*)(o1 + c) = make_float2((acc[nt][2] - mu1) * iv1 * gx + bx,
                                         (acc[nt][3] - mu1) * iv1 * gy + by);
    }
}

// ================= kFoldT: biasA = b1 + hV @ W1[0:128]; zero g_dh =================
#define SFOLD (34816 + 512)
__global__ void __launch_bounds__(256, 1)
kFoldT(const float* __restrict__ x, const float* __restrict__ W,
       const float* __restrict__ b, float* __restrict__ out, int zdh) {
    extern __shared__ char sm[];
    __nv_bfloat16* Ws = (__nv_bfloat16*)sm;
    float* bsm = (float*)(sm + 34816);
    int tid = threadIdx.x, lane = tid & 31, warp = tid >> 5;
    int gid = lane >> 2, tg = lane & 3;
    load_w(W, Ws, 128, tid, 256);
    if (tid < 128) bsm[tid] = b[tid];
    __syncthreads();
    uint32_t loff = (uint32_t)(((lane & 15) * LDW + ((lane >> 4) * 8)) * 2);
    uint32_t wAddr = su32(Ws) + loff;
    for (int wt = blockIdx.x * 8 + warp; wt < NTILES; wt += gridDim.x * 8) {
        int r0 = wt * 16 + gid, r1 = r0 + 8;
        uint32_t af[32];
        float acc[16][4];
        load_af_f32(x + (size_t)r0 * 128, x + (size_t)r1 * 128, tg, af);
        zero16(acc);
        gemm_reg<8>(af, wAddr, acc);
        #pragma unroll
        for (int nt = 0; nt < 16; ++nt) {
            int c = nt * 8 + 2 * tg;
            float2 bb = *(const float2*)(bsm + c);
            *(float2*)(out + (size_t)r0 * 128 + c) = make_float2(acc[nt][0] + bb.x, acc[nt][1] + bb.y);
            *(float2*)(out + (size_t)r1 * 128 + c) = make_float2(acc[nt][2] + bb.x, acc[nt][3] + bb.y);
            if (zdh) {
                *(float2*)(g_dh + (size_t)r0 * 128 + c) = make_float2(0.f, 0.f);
                *(float2*)(g_dh + (size_t)r1 * 128 + c) = make_float2(0.f, 0.f);
            }
        }
    }
}

// ================= kEdge: dual-tile (M=32) register-resident MLP =================
#define KE_SMEM (69632 + 34816 + 34816 + 1024)
__global__ void __launch_bounds__(256, 1)
kEdge(int mode, const float* __restrict__ hE,
      const float* __restrict__ Wl1, const float* __restrict__ Wl2,
      const float* __restrict__ Wl3, int K1,
      const float* __restrict__ b2, const float* __restrict__ b3,
      const float* __restrict__ bias1, const float* __restrict__ matt,
      const int* __restrict__ Eidx, const float* __restrict__ g3,
      const float* __restrict__ bb3, float* __restrict__ outE) {
    extern __shared__ char sm[];
    __nv_bfloat16* W1s = (__nv_bfloat16*)sm;
    float* bs = (float*)(sm + K1 * 272 + 69632);
    int tid = threadIdx.x, lane = tid & 31, warp = tid >> 5;
    int gid = lane >> 2, tg = lane & 3;

    load_w(Wl1, W1s, K1, tid, 256);
    load_w(Wl2, (__nv_bfloat16*)(sm + K1 * 272), 128, tid, 256);
    load_w(Wl3, (__nv_bfloat16*)(sm + K1 * 272 + 34816), 128, tid, 256);
    if (tid < 128) { bs[tid] = b2[tid]; bs[128 + tid] = b3[tid]; }
    __syncthreads();
    float* b2s = bs; float* b3s = bs + 128;

    uint32_t loff = (uint32_t)(((lane & 15) * LDW + ((lane >> 4) * 8)) * 2);
    uint32_t w1Addr = su32(sm) + loff;
    uint32_t w2Addr = w1Addr + K1 * 272;
    uint32_t w3Addr = w2Addr + 34816;

    const int pstride = gridDim.x * 8;
    int p = blockIdx.x * 8 + warp;
    uint32_t afA[32], afB[32];
    float accA[16][4], accB[16][4];
    if (p < PAIRS) {
        int rA = p * 32 + gid;
        load_af_f32(hE + (size_t)rA * 128, hE + (size_t)(rA + 8) * 128, tg, afA);
        load_af_f32(hE + (size_t)(rA + 16) * 128, hE + (size_t)(rA + 24) * 128, tg, afB);
    }
    while (p < PAIRS) {
        int base = p * 32;
        int rA0 = base + gid, rA1 = rA0 + 8, rB0 = rA0 + 16, rB1 = rA0 + 24;
        int nodeA = base / 48, nodeB = (base + 16) / 48;
        int nA0 = 0, nA1 = 0, nB0 = 0, nB1 = 0;
        if (mode) {
            int bbase = (base / 98304) * 2048;
            nA0 = bbase + __ldg(Eidx + rA0);
            nA1 = bbase + __ldg(Eidx + rA1);
            nB0 = bbase + __ldg(Eidx + rB0);
            nB1 = bbase + __ldg(Eidx + rB1);
        }
        zero16(accA); zero16(accB);
        gemm2<8>(afA, afB, w1Addr, accA, accB);
        if (mode) {
            load_af_bf16(g_hvb + (size_t)nA0 * 128, g_hvb + (size_t)nA1 * 128, tg, afA);
            load_af_bf16(g_hvb + (size_t)nB0 * 128, g_hvb + (size_t)nB1 * 128, tg, afB);
            gemm2<8>(afA, afB, w1Addr + 128 * 272, accA, accB);
        }
        pack_gelu(accA, bias1 + (size_t)nodeA * 128, tg, afA);
        pack_gelu(accB, bias1 + (size_t)nodeB * 128, tg, afB);
        zero16(accA); zero16(accB);
        gemm2<8>(afA, afB, w2Addr, accA, accB);
        pack_gelu(accA, b2s, tg, afA);
        pack_gelu(accB, b2s, tg, afB);
        zero16(accA); zero16(accB);
        gemm2<8>(afA, afB, w3Addr, accA, accB);

        int pn = p + pstride;
        if (pn < PAIRS) {   // prefetch both next tiles during epilogue
            int rn = pn * 32 + gid;
            load_af_f32(hE + (size_t)rn * 128, hE + (size_t)(rn + 8) * 128, tg, afA);
            load_af_f32(hE + (size_t)(rn + 16) * 128, hE + (size_t)(rn + 24) * 128, tg, afB);
        }

        if (mode == 0) {
            epi0(accA, matt, rA0, rA1, nodeA, b3s, lane, tg);
            epi0(accB, matt, rB0, rB1, nodeB, b3s, lane, tg);
        } else {
            epi1(accA, hE, outE, rA0, rA1, b3s, g3, bb3, tg);
            epi1(accB, hE, outE, rB0, rB1, b3s, g3, bb3, tg);
        }
        p = pn;
    }
}

// ============ kF1 (fused LN1): v1 = LN1(hV + dh/30); g_fb = gelu(v1 @ Win + bin) =====
#define SF1 (4 * 34816 + 2048 + 1024)
__global__ void __launch_bounds__(256, 1)
kF1(const float* __restrict__ hV, const float* __restrict__ Win,
    const float* __restrict__ bin, const float* __restrict__ g1,
    const float* __restrict__ bb1) {
    extern __shared__ char sm[];
    float* bin_s = (float*)(sm + 4 * 34816);
    float* g1s = bin_s + 512;
    float* b1s = g1s + 128;
    int tid = threadIdx.x, lane = tid & 31, warp = tid >> 5;
    int gid = lane >> 2, tg = lane & 3;
    for (int i = tid; i < 16384; i += 256) {
        float4 w = ((const float4*)Win)[i];
        int k = i >> 7, n = (i * 4) & 511;
        __nv_bfloat16* dst = (__nv_bfloat16*)(sm + (n >> 7) * 34816);
        int cc = n & 127;
        *(__nv_bfloat162*)(dst + k * LDW + cc)     = __floats2bfloat162_rn(w.x, w.y);
        *(__nv_bfloat162*)(dst + k * LDW + cc + 2) = __floats2bfloat162_rn(w.z, w.w);
    }
    for (int i = tid; i < 512; i += 256) bin_s[i] = bin[i];
    if (tid < 128) { g1s[tid] = g1[tid]; b1s[tid] = bb1[tid]; }
    __syncthreads();
    uint32_t loff = (uint32_t)(((lane & 15) * LDW + ((lane >> 4) * 8)) * 2);

    for (int wt = blockIdx.x * 8 + warp; wt < NTILES; wt += gridDim.x * 8) {
        int r0 = wt * 16 + gid, r1 = r0 + 8;
        const float* hv0 = hV + (size_t)r0 * 128;
        const float* hv1 = hV + (size_t)r1 * 128;
        const float* dh0 = g_dh + (size_t)r0 * 128;
        const float* dh1 = g_dh + (size_t)r1 * 128;
        float x0[32], x1[32];
        float sum0 = 0.f, sq0 = 0.f, sum1 = 0.f, sq1 = 0.f;
        #pragma unroll
        for (int j = 0; j < 16; ++j) {
            int c = (j >> 1) * 16 + (j & 1) * 8 + 2 * tg;
            float2 a0 = *(const float2*)(hv0 + c);
            float2 d0 = *(const float2*)(dh0 + c);
            float2 a1 = *(const float2*)(hv1 + c);
            float2 d1 = *(const float2*)(dh1 + c);
            x0[2 * j]     = a0.x + d0.x * (1.0f / 30.0f);
            x0[2 * j + 1] = a0.y + d0.y * (1.0f / 30.0f);
            x1[2 * j]     = a1.x + d1.x * (1.0f / 30.0f);
            x1[2 * j + 1] = a1.y + d1.y * (1.0f / 30.0f);
            sum0 += x0[2 * j] + x0[2 * j + 1];
            sq0  += x0[2 * j] * x0[2 * j] + x0[2 * j + 1] * x0[2 * j + 1];
            sum1 += x1[2 * j] + x1[2 * j + 1];
            sq1  += x1[2 * j] * x1[2 * j] + x1[2 * j + 1] * x1[2 * j + 1];
        }
        #pragma unroll
        for (int o = 1; o < 4; o <<= 1) {
            sum0 += __shfl_xor_sync(~0u, sum0, o);
            sq0  += __shfl_xor_sync(~0u, sq0, o);
            sum1 += __shfl_xor_sync(~0u, sum1, o);
            sq1  += __shfl_xor_sync(~0u, sq1, o);
        }
        float mu0 = sum0 * (1.0f / 128.0f);
        float iv0 = rsqrtf(sq0 * (1.0f / 128.0f) - mu0 * mu0 + 1e-5f);
        float mu1 = sum1 * (1.0f / 128.0f);
        float iv1 = rsqrtf(sq1 * (1.0f / 128.0f) - mu1 * mu1 + 1e-5f);
        uint32_t af[32];
        #pragma unroll
        for (int j = 0; j < 16; ++j) {
            int c = (j >> 1) * 16 + (j & 1) * 8 + 2 * tg;
            float y0a = (x0[2 * j] - mu0) * iv0 * g1s[c] + b1s[c];
            float y0b = (x0[2 * j + 1] - mu0) * iv0 * g1s[c + 1] + b1s[c + 1];
            float y1a = (x1[2 * j] - mu1) * iv1 * g1s[c] + b1s[c];
            float y1b = (x1[2 * j + 1] - mu1) * iv1 * g1s[c + 1] + b1s[c + 1];
            *(float2*)(g_v1 + (size_t)r0 * 128 + c) = make_float2(y0a, y0b);
            *(float2*)(g_v1 + (size_t)r1 * 128 + c) = make_float2(y1a, y1b);
            int kt = j >> 1, half = j & 1;
            af[4 * kt + 2 * half]     = pk(y0a, y0b);
            af[4 * kt + 2 * half + 1] = pk(y1a, y1b);
        }
        float acc[16][4];
        #pragma unroll
        for (int ng = 0; ng < 4; ++ng) {
            zero16(acc);
            gemm_reg<8>(af, su32(sm + ng * 34816) + loff, acc);
            #pragma unroll
            for (int nt = 0; nt < 16; ++nt) {
                int cg = ng * 128 + nt * 8 + 2 * tg;
                float2 b = *(const float2*)(bin_s + cg);
                *(uint32_t*)(g_fb + (size_t)r0 * 512 + cg) =
                    pk(gelu_f(acc[nt][0] + b.x), gelu_f(acc[nt][1] + b.y));
                *(uint32_t*)(g_fb + (size_t)r1 * 512 + cg) =
                    pk(gelu_f(acc[nt][2] + b.x), gelu_f(acc[nt][3] + b.y));
            }
        }
    }
}

// ==== kF2 (fused fold): outV = mask*LN2(v1 + fb@Wout + bout); biasC = b11 + outV@W11 ==
#define SF2 (139264 + 34816 + 2048)
__global__ void __launch_bounds__(256, 1)
kF2(const float* __restrict__ Wout, const float* __restrict__ bout,
    const float* __restrict__ g2, const float* __restrict__ bb2,
    const float* __restrict__ maskV, float* __restrict__ outV,
    const float* __restrict__ W11, const float* __restrict__ b11,
    float* __restrict__ biasC) {
    extern __shared__ char sm[];
    __nv_bfloat16* Ws = (__nv_bfloat16*)sm;
    __nv_bfloat16* W11s = (__nv_bfloat16*)(sm + 139264);
    float* bs = (float*)(sm + 139264 + 34816);
    int tid = threadIdx.x, lane = tid & 31, warp = tid >> 5;
    int gid = lane >> 2, tg = lane & 3;
    load_w(Wout, Ws, 512, tid, 256);
    load_w(W11, W11s, 128, tid, 256);
    if (tid < 128) { bs[tid] = bout[tid]; bs[128 + tid] = g2[tid];
                     bs[256 + tid] = bb2[tid]; bs[384 + tid] = b11[tid]; }
    __syncthreads();
    float* bo = bs; float* g2s = bs + 128; float* b2s = bs + 256; float* b11s = bs + 384;
    uint32_t loff = (uint32_t)(((lane & 15) * LDW + ((lane >> 4) * 8)) * 2);
    uint32_t wAddr = su32(Ws) + loff;
    uint32_t w11Addr = su32(W11s) + loff;

    for (int wt = blockIdx.x * 8 + warp; wt < NTILES; wt += gridDim.x * 8) {
        int r0 = wt * 16 + gid, r1 = r0 + 8;
        const __nv_bfloat16* f0 = g_fb + (size_t)r0 * 512;
        const __nv_bfloat16* f1 = g_fb + (size_t)r1 * 512;
        float acc[16][4];
        zero16(acc);
        #pragma unroll 4
        for (int kt = 0; kt < 32; ++kt) {
            uint32_t a[4];
            int c = kt * 16 + 2 * tg;
            a[0] = *(const uint32_t*)(f0 + c);
            a[1] = *(const uint32_t*)(f1 + c);
            a[2] = *(const uint32_t*)(f0 + c + 8);
            a[3] = *(const uint32_t*)(f1 + c + 8);
            #pragma unroll
            for (int nb = 0; nb < 8; ++nb) {
                uint32_t b[4];
                asm volatile("ldmatrix.sync.aligned.m8n8.x4.trans.shared.b16 {%0,%1,%2,%3},[%4];"
                             : "=r"(b[0]), "=r"(b[1]), "=r"(b[2]), "=r"(b[3])
                             : "r"(wAddr + kt * 4352 + nb * 32));
                MMA4(acc[2 * nb],     a, b[0], b[1]);
                MMA4(acc[2 * nb + 1], a, b[2], b[3]);
            }
        }
        const float* v0 = g_v1 + (size_t)r0 * 128;
        const float* v1 = g_v1 + (size_t)r1 * 128;
        float sum0 = 0.f, sq0 = 0.f, sum1 = 0.f, sq1 = 0.f;
        #pragma unroll
        for (int nt = 0; nt < 16; ++nt) {
            int c = nt * 8 + 2 * tg;
            float2 b  = *(const float2*)(bo + c);
            float2 h0 = *(const float2*)(v0 + c);
            float2 h1 = *(const float2*)(v1 + c);
            acc[nt][0] += b.x + h0.x; acc[nt][1] += b.y + h0.y;
            acc[nt][2] += b.x + h1.x; acc[nt][3] += b.y + h1.y;
            sum0 += acc[nt][0] + acc[nt][1];
            sq0  += acc[nt][0] * acc[nt][0] + acc[nt][1] * acc[nt][1];
            sum1 += acc[nt][2] + acc[nt][3];
            sq1  += acc[nt][2] * acc[nt][2] + acc[nt][3] * acc[nt][3];
        }
        #pragma unroll
        for (int o = 1; o < 4; o <<= 1) {
            sum0 += __shfl_xor_sync(~0u, sum0, o);
            sq0  += __shfl_xor_sync(~0u, sq0, o);
            sum1 += __shfl_xor_sync(~0u, sum1, o);
            sq1  += __shfl_xor_sync(~0u, sq1, o);
        }
        float mu0 = sum0 * (1.0f / 128.0f);
        float iv0 = rsqrtf(sq0 * (1.0f / 128.0f) - mu0 * mu0 + 1e-5f);
        float mu1 = sum1 * (1.0f / 128.0f);
        float iv1 = rsqrtf(sq1 * (1.0f / 128.0f) - mu1 * mu1 + 1e-5f);
        float mv0 = __ldg(maskV + r0), mv1 = __ldg(maskV + r1);
        uint32_t af[32];
        #pragma unroll
        for (int nt = 0; nt < 16; ++nt) {
            int c = nt * 8 + 2 * tg;
            float gx = g2s[c], gy = g2s[c + 1], bx = b2s[c], by = b2s[c + 1];
            float2 y0 = { ((acc[nt][0] - mu0) * iv0 * gx + bx) * mv0,
                          ((acc[nt][1] - mu0) * iv0 * gy + by) * mv0 };
            float2 y1 = { ((acc[nt][2] - mu1) * iv1 * gx + bx) * mv1,
                          ((acc[nt][3] - mu1) * iv1 * gy + by) * mv1 };
            *(float2*)(outV + (size_t)r0 * 128 + c) = y0;
            *(float2*)(outV + (size_t)r1 * 128 + c) = y1;
            uint32_t p0 = pk(y0.x, y0.y), p1 = pk(y1.x, y1.y);
            *(uint32_t*)(g_hvb + (size_t)r0 * 128 + c) = p0;
            *(uint32_t*)(g_hvb + (size_t)r1 * 128 + c) = p1;
            int kt = nt >> 1, half = nt & 1;
            af[4 * kt + 2 * half]     = p0;
            af[4 * kt + 2 * half + 1] = p1;
        }
        zero16(acc);
        gemm_reg<8>(af, w11Addr, acc);
        #pragma unroll
        for (int nt = 0; nt < 16; ++nt) {
            int c = nt * 8 + 2 * tg;
            float2 bb = *(const float2*)(b11s + c);
            *(float2*)(biasC + (size_t)r0 * 128 + c) = make_float2(acc[nt][0] + bb.x, acc[nt][1] + bb.y);
            *(float2*)(biasC + (size_t)r1 * 128 + c) = make_float2(acc[nt][2] + bb.x, acc[nt][3] + bb.y);
        }
    }
}

extern "C" void kernel_launch(void* const* d_in, const int* in_sizes, int n_in,
                              void* d_out, int out_size) {
    const float* hV = (const float*)d_in[0];
    const float* hE = (const float*)d_in[1];
    const float* mV = (const float*)d_in[2];
    const int* Eidx = (const int*)d_in[3];
    const float* matt = (const float*)d_in[4];
    const float* W1 = (const float*)d_in[5],  *b1 = (const float*)d_in[6];
    const float* W2 = (const float*)d_in[7],  *b2 = (const float*)d_in[8];
    const float* W3 = (const float*)d_in[9],  *b3 = (const float*)d_in[10];
    const float* W11 = (const float*)d_in[11], *b11 = (const float*)d_in[12];
    const float* W12 = (const float*)d_in[13], *b12 = (const float*)d_in[14];
    const float* W13 = (const float*)d_in[15], *b13 = (const float*)d_in[16];
    const float* Win = (const float*)d_in[17], *bin = (const float*)d_in[18];
    const float* Wout = (const float*)d_in[19], *bout = (const float*)d_in[20];
    const float* g1 = (const float*)d_in[21], *bb1 = (const float*)d_in[22];
    const float* g2 = (const float*)d_in[23], *bb2 = (const float*)d_in[24];
    const float* g3 = (const float*)d_in[25], *bb3 = (const float*)d_in[26];
    float* outV = (float*)d_out;
    float* outE = (float*)d_out + HV_ELEMS;
    float* biasA; cudaGetSymbolAddress((void**)&biasA, g_biasA);
    float* biasC; cudaGetSymbolAddress((void**)&biasC, g_biasC);

    cudaFuncSetAttribute(kFoldT, cudaFuncAttributeMaxDynamicSharedMemorySize, SFOLD);
    cudaFuncSetAttribute(kEdge, cudaFuncAttributeMaxDynamicSharedMemorySize, KE_SMEM);
    cudaFuncSetAttribute(kF1, cudaFuncAttributeMaxDynamicSharedMemorySize, SF1);
    cudaFuncSetAttribute(kF2, cudaFuncAttributeMaxDynamicSharedMemorySize, SF2);

    kFoldT<<<64, 256, SFOLD>>>(hV, W1, b1, biasA, 1);
    kEdge<<<148, 256, 104448 + 1024>>>(0, hE, W1 + 128 * 128, W2, W3, 128, b2, b3,
                                       biasA, matt, nullptr, nullptr, nullptr, nullptr);
    kF1<<<64, 256, SF1>>>(hV, Win, bin, g1, bb1);
    kF2<<<64, 256, SF2>>>(Wout, bout, g2, bb2, mV, outV, W11, b11, biasC);
    kEdge<<<148, 256, KE_SMEM>>>(1, hE, W11 + 128 * 128, W12, W13, 256, b12, b13,
                                 biasC, nullptr, Eidx, g3, bb3, outE);
}

// round 13
// speedup vs baseline: 1.1206x; 1.1206x over previous
#include <cuda_runtime.h>
#include <cuda_bf16.h>
#include <cstdint>

#define NODES 8192
#define H_ 128
#define K_ 48
#define EDGES (NODES * K_)
#define WTILES (EDGES / 16)
#define NTILES (NODES / 16)
#define HV_ELEMS (NODES * H_)
#define LDW 136

__device__ __align__(16) float         g_v1[NODES * H_];
__device__ __align__(16) __nv_bfloat16 g_fb[NODES * 512];
__device__ __align__(16) __nv_bfloat16 g_hvb[NODES * H_];
__device__ __align__(16) float         g_dh[NODES * H_];
__device__ __align__(16) float         g_biasA[NODES * H_];
__device__ __align__(16) float         g_biasC[NODES * H_];

static __device__ __forceinline__ unsigned su32(const void* p) {
    return (unsigned)__cvta_generic_to_shared(p);
}
static __device__ __forceinline__ float gelu_f(float x) {
    float u = 0.7978845608028654f * (x + 0.044715f * x * x * x), t;
    asm("tanh.approx.f32 %0, %1;" : "=f"(t) : "f"(u));
    return 0.5f * x * (1.0f + t);
}
static __device__ __forceinline__ uint32_t pk(float x, float y) {
    __nv_bfloat162 h = __floats2bfloat162_rn(x, y);
    return *(uint32_t*)&h;
}
static __device__ __forceinline__ void load_w(const float* g, __nv_bfloat16* s,
                                              int rows, int tid, int nthr) {
    int total4 = rows * 32;
    for (int i = tid; i < total4; i += nthr) {
        float4 w = ((const float4*)g)[i];
        int r = (i * 4) >> 7, c = (i * 4) & 127;
        *(__nv_bfloat162*)(s + r * LDW + c)     = __floats2bfloat162_rn(w.x, w.y);
        *(__nv_bfloat162*)(s + r * LDW + c + 2) = __floats2bfloat162_rn(w.z, w.w);
    }
}

#define MMA4(ac, a, b0, b1) \
    asm volatile("mma.sync.aligned.m16n8k16.row.col.f32.bf16.bf16.f32 " \
                 "{%0,%1,%2,%3},{%4,%5,%6,%7},{%8,%9},{%0,%1,%2,%3};" \
                 : "+f"((ac)[0]), "+f"((ac)[1]), "+f"((ac)[2]), "+f"((ac)[3]) \
                 : "r"((a)[0]), "r"((a)[1]), "r"((a)[2]), "r"((a)[3]), \
                   "r"(b0), "r"(b1))

static __device__ __forceinline__ void zero16(float acc[16][4]) {
    #pragma unroll
    for (int i = 0; i < 16; ++i)
        #pragma unroll
        for (int j = 0; j < 4; ++j) acc[i][j] = 0.0f;
}

template <int NKT>
static __device__ __forceinline__ void gemm_reg(const uint32_t* af, uint32_t wAddr,
                                                float acc[16][4]) {
    #pragma unroll
    for (int kt = 0; kt < NKT; ++kt) {
        #pragma unroll
        for (int nb = 0; nb < 8; ++nb) {
            uint32_t b[4];
            asm volatile("ldmatrix.sync.aligned.m8n8.x4.trans.shared.b16 {%0,%1,%2,%3},[%4];"
                         : "=r"(b[0]), "=r"(b[1]), "=r"(b[2]), "=r"(b[3])
                         : "r"(wAddr + kt * 4352 + nb * 32));
            MMA4(acc[2 * nb],     af + 4 * kt, b[0], b[1]);
            MMA4(acc[2 * nb + 1], af + 4 * kt, b[2], b[3]);
        }
    }
}

static __device__ __forceinline__ void load_af_f32(const float* r0, const float* r1,
                                                   int tg, uint32_t af[32]) {
    #pragma unroll
    for (int kt = 0; kt < 8; ++kt) {
        int c = kt * 16 + 2 * tg;
        float2 v0 = *(const float2*)(r0 + c);
        float2 v1 = *(const float2*)(r1 + c);
        float2 v2 = *(const float2*)(r0 + c + 8);
        float2 v3 = *(const float2*)(r1 + c + 8);
        af[4 * kt]     = pk(v0.x, v0.y);
        af[4 * kt + 1] = pk(v1.x, v1.y);
        af[4 * kt + 2] = pk(v2.x, v2.y);
        af[4 * kt + 3] = pk(v3.x, v3.y);
    }
}
static __device__ __forceinline__ void load_af_bf16(const __nv_bfloat16* r0,
                                                    const __nv_bfloat16* r1,
                                                    int tg, uint32_t af[32]) {
    #pragma unroll
    for (int kt = 0; kt < 8; ++kt) {
        int c = kt * 16 + 2 * tg;
        af[4 * kt]     = *(const uint32_t*)(r0 + c);
        af[4 * kt + 1] = *(const uint32_t*)(r1 + c);
        af[4 * kt + 2] = *(const uint32_t*)(r0 + c + 8);
        af[4 * kt + 3] = *(const uint32_t*)(r1 + c + 8);
    }
}
static __device__ __forceinline__ void pack_gelu(const float acc[16][4],
                                                 const float* bias, int tg,
                                                 uint32_t af[32]) {
    #pragma unroll
    for (int kt = 0; kt < 8; ++kt) {
        int n0 = 2 * kt, n1 = 2 * kt + 1;
        float2 bA = *(const float2*)(bias + n0 * 8 + 2 * tg);
        float2 bB = *(const float2*)(bias + n1 * 8 + 2 * tg);
        af[4 * kt]     = pk(gelu_f(acc[n0][0] + bA.x), gelu_f(acc[n0][1] + bA.y));
        af[4 * kt + 1] = pk(gelu_f(acc[n0][2] + bA.x), gelu_f(acc[n0][3] + bA.y));
        af[4 * kt + 2] = pk(gelu_f(acc[n1][0] + bB.x), gelu_f(acc[n1][1] + bB.y));
        af[4 * kt + 3] = pk(gelu_f(acc[n1][2] + bB.x), gelu_f(acc[n1][3] + bB.y));
    }
}

// ================= kFoldT: biasA = b1 + hV @ W1[0:128]; zero g_dh =================
#define SFOLD (34816 + 512)
__global__ void __launch_bounds__(256, 1)
kFoldT(const float* __restrict__ x, const float* __restrict__ W,
       const float* __restrict__ b, float* __restrict__ out, int zdh) {
    extern __shared__ char sm[];
    __nv_bfloat16* Ws = (__nv_bfloat16*)sm;
    float* bsm = (float*)(sm + 34816);
    int tid = threadIdx.x, lane = tid & 31, warp = tid >> 5;
    int gid = lane >> 2, tg = lane & 3;
    load_w(W, Ws, 128, tid, 256);
    if (tid < 128) bsm[tid] = b[tid];
    __syncthreads();
    uint32_t loff = (uint32_t)(((lane & 15) * LDW + ((lane >> 4) * 8)) * 2);
    uint32_t wAddr = su32(Ws) + loff;
    for (int wt = blockIdx.x * 8 + warp; wt < NTILES; wt += gridDim.x * 8) {
        int r0 = wt * 16 + gid, r1 = r0 + 8;
        uint32_t af[32];
        float acc[16][4];
        load_af_f32(x + (size_t)r0 * 128, x + (size_t)r1 * 128, tg, af);
        zero16(acc);
        gemm_reg<8>(af, wAddr, acc);
        #pragma unroll
        for (int nt = 0; nt < 16; ++nt) {
            int c = nt * 8 + 2 * tg;
            float2 bb = *(const float2*)(bsm + c);
            *(float2*)(out + (size_t)r0 * 128 + c) = make_float2(acc[nt][0] + bb.x, acc[nt][1] + bb.y);
            *(float2*)(out + (size_t)r1 * 128 + c) = make_float2(acc[nt][2] + bb.x, acc[nt][3] + bb.y);
            if (zdh) {
                *(float2*)(g_dh + (size_t)r0 * 128 + c) = make_float2(0.f, 0.f);
                *(float2*)(g_dh + (size_t)r1 * 128 + c) = make_float2(0.f, 0.f);
            }
        }
    }
}

// ================= kEdge: M=16 register-resident MLP, 512 thr, prefetch (R11 base) ====
#define KE_SMEM (69632 + 34816 + 34816 + 2048)
__global__ void __launch_bounds__(512, 1)
kEdge(int mode, const float* __restrict__ hE,
      const float* __restrict__ Wl1, const float* __restrict__ Wl2,
      const float* __restrict__ Wl3, int K1,
      const float* __restrict__ b2, const float* __restrict__ b3,
      const float* __restrict__ bias1, const float* __restrict__ matt,
      const int* __restrict__ Eidx, const float* __restrict__ g3,
      const float* __restrict__ bb3, float* __restrict__ outE) {
    extern __shared__ char sm[];
    __nv_bfloat16* W1s = (__nv_bfloat16*)sm;
    float* bs = (float*)(sm + K1 * 272 + 69632);
    int tid = threadIdx.x, lane = tid & 31, warp = tid >> 5;
    int gid = lane >> 2, tg = lane & 3;

    load_w(Wl1, W1s, K1, tid, 512);
    load_w(Wl2, (__nv_bfloat16*)(sm + K1 * 272), 128, tid, 512);
    load_w(Wl3, (__nv_bfloat16*)(sm + K1 * 272 + 34816), 128, tid, 512);
    if (tid < 128) {
        bs[tid] = b2[tid]; bs[128 + tid] = b3[tid];
        if (mode) { bs[256 + tid] = g3[tid]; bs[384 + tid] = bb3[tid]; }
    }
    __syncthreads();
    float* b2s = bs; float* b3s = bs + 128; float* g3s = bs + 256; float* bb3s = bs + 384;

    uint32_t loff = (uint32_t)(((lane & 15) * LDW + ((lane >> 4) * 8)) * 2);
    uint32_t w1Addr = su32(sm) + loff;
    uint32_t w2Addr = w1Addr + K1 * 272;
    uint32_t w3Addr = w2Addr + 34816;

    const int stride = gridDim.x * 16;
    int wt = blockIdx.x * 16 + warp;
    uint32_t af[32];
    float acc[16][4];
    if (wt < WTILES) {
        int r0 = wt * 16 + gid;
        load_af_f32(hE + (size_t)r0 * 128, hE + (size_t)(r0 + 8) * 128, tg, af);
    }
    while (wt < WTILES) {
        int rowbase = wt * 16;
        int r0 = rowbase + gid, r1 = r0 + 8;
        int node = rowbase / 48;
        int nb0 = 0, nb1 = 0;
        if (mode) {
            int bbase = (rowbase / 98304) * 2048;
            nb0 = bbase + Eidx[r0];
            nb1 = bbase + Eidx[r1];
        }
        zero16(acc);
        gemm_reg<8>(af, w1Addr, acc);
        if (mode) {
            load_af_bf16(g_hvb + (size_t)nb0 * 128, g_hvb + (size_t)nb1 * 128, tg, af);
            gemm_reg<8>(af, w1Addr + 128 * 272, acc);
        }
        pack_gelu(acc, bias1 + (size_t)node * 128, tg, af);
        zero16(acc);
        gemm_reg<8>(af, w2Addr, acc);
        pack_gelu(acc, b2s, tg, af);
        zero16(acc);
        gemm_reg<8>(af, w3Addr, acc);

        int wtn = wt + stride;
        if (wtn < WTILES) {
            int rn = wtn * 16 + gid;
            load_af_f32(hE + (size_t)rn * 128, hE + (size_t)(rn + 8) * 128, tg, af);
        }

        if (mode == 0) {
            float m0 = __ldg(matt + r0), m1 = __ldg(matt + r1);
            #pragma unroll
            for (int nt = 0; nt < 16; ++nt) {
                float2 b = *(const float2*)(b3s + nt * 8 + 2 * tg);
                acc[nt][0] = (acc[nt][0] + b.x) * m0 + (acc[nt][2] + b.x) * m1;
                acc[nt][1] = (acc[nt][1] + b.y) * m0 + (acc[nt][3] + b.y) * m1;
            }
            #pragma unroll
            for (int o = 4; o < 32; o <<= 1)
                #pragma unroll
                for (int nt = 0; nt < 16; ++nt) {
                    acc[nt][0] += __shfl_xor_sync(~0u, acc[nt][0], o);
                    acc[nt][1] += __shfl_xor_sync(~0u, acc[nt][1], o);
                }
            if (lane < 4) {
                float* dst = g_dh + (size_t)node * 128;
                #pragma unroll
                for (int nt = 0; nt < 16; ++nt) {
                    atomicAdd(dst + nt * 8 + 2 * lane,     acc[nt][0]);
                    atomicAdd(dst + nt * 8 + 2 * lane + 1, acc[nt][1]);
                }
            }
        } else {
            const float* e0 = hE + (size_t)r0 * 128;
            const float* e1 = hE + (size_t)r1 * 128;
            float sum0 = 0.f, sq0 = 0.f, sum1 = 0.f, sq1 = 0.f;
            #pragma unroll
            for (int nt = 0; nt < 16; ++nt) {
                int c = nt * 8 + 2 * tg;
                float2 b  = *(const float2*)(b3s + c);
                float2 h0 = *(const float2*)(e0 + c);
                float2 h1 = *(const float2*)(e1 + c);
                acc[nt][0] += b.x + h0.x; acc[nt][1] += b.y + h0.y;
                acc[nt][2] += b.x + h1.x; acc[nt][3] += b.y + h1.y;
                sum0 += acc[nt][0] + acc[nt][1];
                sq0  += acc[nt][0] * acc[nt][0] + acc[nt][1] * acc[nt][1];
                sum1 += acc[nt][2] + acc[nt][3];
                sq1  += acc[nt][2] * acc[nt][2] + acc[nt][3] * acc[nt][3];
            }
            #pragma unroll
            for (int o = 1; o < 4; o <<= 1) {
                sum0 += __shfl_xor_sync(~0u, sum0, o);
                sq0  += __shfl_xor_sync(~0u, sq0, o);
                sum1 += __shfl_xor_sync(~0u, sum1, o);
                sq1  += __shfl_xor_sync(~0u, sq1, o);
            }
            float mu0 = sum0 * (1.0f / 128.0f);
            float iv0 = rsqrtf(sq0 * (1.0f / 128.0f) - mu0 * mu0 + 1e-5f);
            float mu1 = sum1 * (1.0f / 128.0f);
            float iv1 = rsqrtf(sq1 * (1.0f / 128.0f) - mu1 * mu1 + 1e-5f);
            float* o0 = outE + (size_t)r0 * 128;
            float* o1 = outE + (size_t)r1 * 128;
            #pragma unroll
            for (int nt = 0; nt < 16; ++nt) {
                int c = nt * 8 + 2 * tg;
                float gx = g3s[c], gy = g3s[c + 1];
                float bx = bb3s[c], by = bb3s[c + 1];
                *(float2*)(o0 + c) = make_float2((acc[nt][0] - mu0) * iv0 * gx + bx,
                                                 (acc[nt][1] - mu0) * iv0 * gy + by);
                *(float2*)(o1 + c) = make_float2((acc[nt][2] - mu1) * iv1 * gx + bx,
                                                 (acc[nt][3] - mu1) * iv1 * gy + by);
            }
        }
        wt = wtn;
    }
}

// ============ kF1 (fused LN1): v1 = LN1(hV + dh/30); g_fb = gelu(v1 @ Win + bin) =====
#define SF1 (4 * 34816 + 2048 + 1024)
__global__ void __launch_bounds__(256, 1)
kF1(const float* __restrict__ hV, const float* __restrict__ Win,
    const float* __restrict__ bin, const float* __restrict__ g1,
    const float* __restrict__ bb1) {
    extern __shared__ char sm[];
    float* bin_s = (float*)(sm + 4 * 34816);
    float* g1s = bin_s + 512;
    float* b1s = g1s + 128;
    int tid = threadIdx.x, lane = tid & 31, warp = tid >> 5;
    int gid = lane >> 2, tg = lane & 3;
    for (int i = tid; i < 16384; i += 256) {
        float4 w = ((const float4*)Win)[i];
        int k = i >> 7, n = (i * 4) & 511;
        __nv_bfloat16* dst = (__nv_bfloat16*)(sm + (n >> 7) * 34816);
        int cc = n & 127;
        *(__nv_bfloat162*)(dst + k * LDW + cc)     = __floats2bfloat162_rn(w.x, w.y);
        *(__nv_bfloat162*)(dst + k * LDW + cc + 2) = __floats2bfloat162_rn(w.z, w.w);
    }
    for (int i = tid; i < 512; i += 256) bin_s[i] = bin[i];
    if (tid < 128) { g1s[tid] = g1[tid]; b1s[tid] = bb1[tid]; }
    __syncthreads();
    uint32_t loff = (uint32_t)(((lane & 15) * LDW + ((lane >> 4) * 8)) * 2);

    for (int wt = blockIdx.x * 8 + warp; wt < NTILES; wt += gridDim.x * 8) {
        int r0 = wt * 16 + gid, r1 = r0 + 8;
        const float* hv0 = hV + (size_t)r0 * 128;
        const float* hv1 = hV + (size_t)r1 * 128;
        const float* dh0 = g_dh + (size_t)r0 * 128;
        const float* dh1 = g_dh + (size_t)r1 * 128;
        float x0[32], x1[32];
        float sum0 = 0.f, sq0 = 0.f, sum1 = 0.f, sq1 = 0.f;
        #pragma unroll
        for (int j = 0; j < 16; ++j) {
            int c = (j >> 1) * 16 + (j & 1) * 8 + 2 * tg;
            float2 a0 = *(const float2*)(hv0 + c);
            float2 d0 = *(const float2*)(dh0 + c);
            float2 a1 = *(const float2*)(hv1 + c);
            float2 d1 = *(const float2*)(dh1 + c);
            x0[2 * j]     = a0.x + d0.x * (1.0f / 30.0f);
            x0[2 * j + 1] = a0.y + d0.y * (1.0f / 30.0f);
            x1[2 * j]     = a1.x + d1.x * (1.0f / 30.0f);
            x1[2 * j + 1] = a1.y + d1.y * (1.0f / 30.0f);
            sum0 += x0[2 * j] + x0[2 * j + 1];
            sq0  += x0[2 * j] * x0[2 * j] + x0[2 * j + 1] * x0[2 * j + 1];
            sum1 += x1[2 * j] + x1[2 * j + 1];
            sq1  += x1[2 * j] * x1[2 * j] + x1[2 * j + 1] * x1[2 * j + 1];
        }
        #pragma unroll
        for (int o = 1; o < 4; o <<= 1) {
            sum0 += __shfl_xor_sync(~0u, sum0, o);
            sq0  += __shfl_xor_sync(~0u, sq0, o);
            sum1 += __shfl_xor_sync(~0u, sum1, o);
            sq1  += __shfl_xor_sync(~0u, sq1, o);
        }
        float mu0 = sum0 * (1.0f / 128.0f);
        float iv0 = rsqrtf(sq0 * (1.0f / 128.0f) - mu0 * mu0 + 1e-5f);
        float mu1 = sum1 * (1.0f / 128.0f);
        float iv1 = rsqrtf(sq1 * (1.0f / 128.0f) - mu1 * mu1 + 1e-5f);
        uint32_t af[32];
        #pragma unroll
        for (int j = 0; j < 16; ++j) {
            int c = (j >> 1) * 16 + (j & 1) * 8 + 2 * tg;
            float y0a = (x0[2 * j] - mu0) * iv0 * g1s[c] + b1s[c];
            float y0b = (x0[2 * j + 1] - mu0) * iv0 * g1s[c + 1] + b1s[c + 1];
            float y1a = (x1[2 * j] - mu1) * iv1 * g1s[c] + b1s[c];
            float y1b = (x1[2 * j + 1] - mu1) * iv1 * g1s[c + 1] + b1s[c + 1];
            *(float2*)(g_v1 + (size_t)r0 * 128 + c) = make_float2(y0a, y0b);
            *(float2*)(g_v1 + (size_t)r1 * 128 + c) = make_float2(y1a, y1b);
            int kt = j >> 1, half = j & 1;
            af[4 * kt + 2 * half]     = pk(y0a, y0b);
            af[4 * kt + 2 * half + 1] = pk(y1a, y1b);
        }
        float acc[16][4];
        #pragma unroll
        for (int ng = 0; ng < 4; ++ng) {
            zero16(acc);
            gemm_reg<8>(af, su32(sm + ng * 34816) + loff, acc);
            #pragma unroll
            for (int nt = 0; nt < 16; ++nt) {
                int cg = ng * 128 + nt * 8 + 2 * tg;
                float2 b = *(const float2*)(bin_s + cg);
                *(uint32_t*)(g_fb + (size_t)r0 * 512 + cg) =
                    pk(gelu_f(acc[nt][0] + b.x), gelu_f(acc[nt][1] + b.y));
                *(uint32_t*)(g_fb + (size_t)r1 * 512 + cg) =
                    pk(gelu_f(acc[nt][2] + b.x), gelu_f(acc[nt][3] + b.y));
            }
        }
    }
}

// ==== kF2 (fused fold): outV = mask*LN2(v1 + fb@Wout + bout); biasC = b11 + outV@W11 ==
#define SF2 (139264 + 34816 + 2048)
__global__ void __launch_bounds__(256, 1)
kF2(const float* __restrict__ Wout, const float* __restrict__ bout,
    const float* __restrict__ g2, const float* __restrict__ bb2,
    const float* __restrict__ maskV, float* __restrict__ outV,
    const float* __restrict__ W11, const float* __restrict__ b11,
    float* __restrict__ biasC) {
    extern __shared__ char sm[];
    __nv_bfloat16* Ws = (__nv_bfloat16*)sm;
    __nv_bfloat16* W11s = (__nv_bfloat16*)(sm + 139264);
    float* bs = (float*)(sm + 139264 + 34816);
    int tid = threadIdx.x, lane = tid & 31, warp = tid >> 5;
    int gid = lane >> 2, tg = lane & 3;
    load_w(Wout, Ws, 512, tid, 256);
    load_w(W11, W11s, 128, tid, 256);
    if (tid < 128) { bs[tid] = bout[tid]; bs[128 + tid] = g2[tid];
                     bs[256 + tid] = bb2[tid]; bs[384 + tid] = b11[tid]; }
    __syncthreads();
    float* bo = bs; float* g2s = bs + 128; float* b2s = bs + 256; float* b11s = bs + 384;
    uint32_t loff = (uint32_t)(((lane & 15) * LDW + ((lane >> 4) * 8)) * 2);
    uint32_t wAddr = su32(Ws) + loff;
    uint32_t w11Addr = su32(W11s) + loff;

    for (int wt = blockIdx.x * 8 + warp; wt < NTILES; wt += gridDim.x * 8) {
        int r0 = wt * 16 + gid, r1 = r0 + 8;
        const __nv_bfloat16* f0 = g_fb + (size_t)r0 * 512;
        const __nv_bfloat16* f1 = g_fb + (size_t)r1 * 512;
        float acc[16][4];
        zero16(acc);
        #pragma unroll 4
        for (int kt = 0; kt < 32; ++kt) {
            uint32_t a[4];
            int c = kt * 16 + 2 * tg;
            a[0] = *(const uint32_t*)(f0 + c);
            a[1] = *(const uint32_t*)(f1 + c);
            a[2] = *(const uint32_t*)(f0 + c + 8);
            a[3] = *(const uint32_t*)(f1 + c + 8);
            #pragma unroll
            for (int nb = 0; nb < 8; ++nb) {
                uint32_t b[4];
                asm volatile("ldmatrix.sync.aligned.m8n8.x4.trans.shared.b16 {%0,%1,%2,%3},[%4];"
                             : "=r"(b[0]), "=r"(b[1]), "=r"(b[2]), "=r"(b[3])
                             : "r"(wAddr + kt * 4352 + nb * 32));
                MMA4(acc[2 * nb],     a, b[0], b[1]);
                MMA4(acc[2 * nb + 1], a, b[2], b[3]);
            }
        }
        const float* v0 = g_v1 + (size_t)r0 * 128;
        const float* v1 = g_v1 + (size_t)r1 * 128;
        float sum0 = 0.f, sq0 = 0.f, sum1 = 0.f, sq1 = 0.f;
        #pragma unroll
        for (int nt = 0; nt < 16; ++nt) {
            int c = nt * 8 + 2 * tg;
            float2 b  = *(const float2*)(bo + c);
            float2 h0 = *(const float2*)(v0 + c);
            float2 h1 = *(const float2*)(v1 + c);
            acc[nt][0] += b.x + h0.x; acc[nt][1] += b.y + h0.y;
            acc[nt][2] += b.x + h1.x; acc[nt][3] += b.y + h1.y;
            sum0 += acc[nt][0] + acc[nt][1];
            sq0  += acc[nt][0] * acc[nt][0] + acc[nt][1] * acc[nt][1];
            sum1 += acc[nt][2] + acc[nt][3];
            sq1  += acc[nt][2] * acc[nt][2] + acc[nt][3] * acc[nt][3];
        }
        #pragma unroll
        for (int o = 1; o < 4; o <<= 1) {
            sum0 += __shfl_xor_sync(~0u, sum0, o);
            sq0  += __shfl_xor_sync(~0u, sq0, o);
            sum1 += __shfl_xor_sync(~0u, sum1, o);
            sq1  += __shfl_xor_sync(~0u, sq1, o);
        }
        float mu0 = sum0 * (1.0f / 128.0f);
        float iv0 = rsqrtf(sq0 * (1.0f / 128.0f) - mu0 * mu0 + 1e-5f);
        float mu1 = sum1 * (1.0f / 128.0f);
        float iv1 = rsqrtf(sq1 * (1.0f / 128.0f) - mu1 * mu1 + 1e-5f);
        float mv0 = __ldg(maskV + r0), mv1 = __ldg(maskV + r1);
        uint32_t af[32];
        #pragma unroll
        for (int nt = 0; nt < 16; ++nt) {
            int c = nt * 8 + 2 * tg;
            float gx = g2s[c], gy = g2s[c + 1], bx = b2s[c], by = b2s[c + 1];
            float2 y0 = { ((acc[nt][0] - mu0) * iv0 * gx + bx) * mv0,
                          ((acc[nt][1] - mu0) * iv0 * gy + by) * mv0 };
            float2 y1 = { ((acc[nt][2] - mu1) * iv1 * gx + bx) * mv1,
                          ((acc[nt][3] - mu1) * iv1 * gy + by) * mv1 };
            *(float2*)(outV + (size_t)r0 * 128 + c) = y0;
            *(float2*)(outV + (size_t)r1 * 128 + c) = y1;
            uint32_t p0 = pk(y0.x, y0.y), p1 = pk(y1.x, y1.y);
            *(uint32_t*)(g_hvb + (size_t)r0 * 128 + c) = p0;
            *(uint32_t*)(g_hvb + (size_t)r1 * 128 + c) = p1;
            int kt = nt >> 1, half = nt & 1;
            af[4 * kt + 2 * half]     = p0;
            af[4 * kt + 2 * half + 1] = p1;
        }
        zero16(acc);
        gemm_reg<8>(af, w11Addr, acc);
        #pragma unroll
        for (int nt = 0; nt < 16; ++nt) {
            int c = nt * 8 + 2 * tg;
            float2 bb = *(const float2*)(b11s + c);
            *(float2*)(biasC + (size_t)r0 * 128 + c) = make_float2(acc[nt][0] + bb.x, acc[nt][1] + bb.y);
            *(float2*)(biasC + (size_t)r1 * 128 + c) = make_float2(acc[nt][2] + bb.x, acc[nt][3] + bb.y);
        }
    }
}

extern "C" void kernel_launch(void* const* d_in, const int* in_sizes, int n_in,
                              void* d_out, int out_size) {
    const float* hV = (const float*)d_in[0];
    const float* hE = (const float*)d_in[1];
    const float* mV = (const float*)d_in[2];
    const int* Eidx = (const int*)d_in[3];
    const float* matt = (const float*)d_in[4];
    const float* W1 = (const float*)d_in[5],  *b1 = (const float*)d_in[6];
    const float* W2 = (const float*)d_in[7],  *b2 = (const float*)d_in[8];
    const float* W3 = (const float*)d_in[9],  *b3 = (const float*)d_in[10];
    const float* W11 = (const float*)d_in[11], *b11 = (const float*)d_in[12];
    const float* W12 = (const float*)d_in[13], *b12 = (const float*)d_in[14];
    const float* W13 = (const float*)d_in[15], *b13 = (const float*)d_in[16];
    const float* Win = (const float*)d_in[17], *bin = (const float*)d_in[18];
    const float* Wout = (const float*)d_in[19], *bout = (const float*)d_in[20];
    const float* g1 = (const float*)d_in[21], *bb1 = (const float*)d_in[22];
    const float* g2 = (const float*)d_in[23], *bb2 = (const float*)d_in[24];
    const float* g3 = (const float*)d_in[25], *bb3 = (const float*)d_in[26];
    float* outV = (float*)d_out;
    float* outE = (float*)d_out + HV_ELEMS;
    float* biasA; cudaGetSymbolAddress((void**)&biasA, g_biasA);
    float* biasC; cudaGetSymbolAddress((void**)&biasC, g_biasC);

    cudaFuncSetAttribute(kFoldT, cudaFuncAttributeMaxDynamicSharedMemorySize, SFOLD);
    cudaFuncSetAttribute(kEdge, cudaFuncAttributeMaxDynamicSharedMemorySize, KE_SMEM);
    cudaFuncSetAttribute(kF1, cudaFuncAttributeMaxDynamicSharedMemorySize, SF1);
    cudaFuncSetAttribute(kF2, cudaFuncAttributeMaxDynamicSharedMemorySize, SF2);

    kFoldT<<<64, 256, SFOLD>>>(hV, W1, b1, biasA, 1);
    kEdge<<<148, 512, 104448 + 2048>>>(0, hE, W1 + 128 * 128, W2, W3, 128, b2, b3,
                                       biasA, matt, nullptr, g1, bb1, nullptr);
    kF1<<<64, 256, SF1>>>(hV, Win, bin, g1, bb1);
    kF2<<<64, 256, SF2>>>(Wout, bout, g2, bb2, mV, outV, W11, b11, biasC);
    kEdge<<<148, 512, KE_SMEM>>>(1, hE, W11 + 128 * 128, W12, W13, 256, b12, b13,
                                 biasC, nullptr, Eidx, g3, bb3, outE);
}

// round 14
// speedup vs baseline: 1.1353x; 1.0131x over previous
#include <cuda_runtime.h>
#include <cuda_bf16.h>
#include <cstdint>

#define NODES 8192
#define H_ 128
#define K_ 48
#define EDGES (NODES * K_)
#define WTILES (EDGES / 16)
#define NTILES (NODES / 16)
#define HV_ELEMS (NODES * H_)
#define LDW 136

__device__ __align__(16) float         g_v1[NODES * H_];
__device__ __align__(16) __nv_bfloat16 g_fb[NODES * 512];
__device__ __align__(16) __nv_bfloat16 g_hvb[NODES * H_];
__device__ __align__(16) float         g_dh[NODES * H_];
__device__ __align__(16) float         g_biasA[NODES * H_];
__device__ __align__(16) float         g_biasC[NODES * H_];

static __device__ __forceinline__ unsigned su32(const void* p) {
    return (unsigned)__cvta_generic_to_shared(p);
}
static __device__ __forceinline__ float gelu_f(float x) {
    float u = 0.7978845608028654f * (x + 0.044715f * x * x * x), t;
    asm("tanh.approx.f32 %0, %1;" : "=f"(t) : "f"(u));
    return 0.5f * x * (1.0f + t);
}
static __device__ __forceinline__ uint32_t pk(float x, float y) {
    __nv_bfloat162 h = __floats2bfloat162_rn(x, y);
    return *(uint32_t*)&h;
}
static __device__ __forceinline__ void load_w(const float* g, __nv_bfloat16* s,
                                              int rows, int tid, int nthr) {
    int total4 = rows * 32;
    for (int i = tid; i < total4; i += nthr) {
        float4 w = ((const float4*)g)[i];
        int r = (i * 4) >> 7, c = (i * 4) & 127;
        *(__nv_bfloat162*)(s + r * LDW + c)     = __floats2bfloat162_rn(w.x, w.y);
        *(__nv_bfloat162*)(s + r * LDW + c + 2) = __floats2bfloat162_rn(w.z, w.w);
    }
}

#define MMA4(ac, a, b0, b1) \
    asm volatile("mma.sync.aligned.m16n8k16.row.col.f32.bf16.bf16.f32 " \
                 "{%0,%1,%2,%3},{%4,%5,%6,%7},{%8,%9},{%0,%1,%2,%3};" \
                 : "+f"((ac)[0]), "+f"((ac)[1]), "+f"((ac)[2]), "+f"((ac)[3]) \
                 : "r"((a)[0]), "r"((a)[1]), "r"((a)[2]), "r"((a)[3]), \
                   "r"(b0), "r"(b1))

static __device__ __forceinline__ void zero16(float acc[16][4]) {
    #pragma unroll
    for (int i = 0; i < 16; ++i)
        #pragma unroll
        for (int j = 0; j < 4; ++j) acc[i][j] = 0.0f;
}

template <int NKT>
static __device__ __forceinline__ void gemm_reg(const uint32_t* af, uint32_t wAddr,
                                                float acc[16][4]) {
    #pragma unroll
    for (int kt = 0; kt < NKT; ++kt) {
        #pragma unroll
        for (int nb = 0; nb < 8; ++nb) {
            uint32_t b[4];
            asm volatile("ldmatrix.sync.aligned.m8n8.x4.trans.shared.b16 {%0,%1,%2,%3},[%4];"
                         : "=r"(b[0]), "=r"(b[1]), "=r"(b[2]), "=r"(b[3])
                         : "r"(wAddr + kt * 4352 + nb * 32));
            MMA4(acc[2 * nb],     af + 4 * kt, b[0], b[1]);
            MMA4(acc[2 * nb + 1], af + 4 * kt, b[2], b[3]);
        }
    }
}

static __device__ __forceinline__ void load_af_f32(const float* r0, const float* r1,
                                                   int tg, uint32_t af[32]) {
    #pragma unroll
    for (int kt = 0; kt < 8; ++kt) {
        int c = kt * 16 + 2 * tg;
        float2 v0 = *(const float2*)(r0 + c);
        float2 v1 = *(const float2*)(r1 + c);
        float2 v2 = *(const float2*)(r0 + c + 8);
        float2 v3 = *(const float2*)(r1 + c + 8);
        af[4 * kt]     = pk(v0.x, v0.y);
        af[4 * kt + 1] = pk(v1.x, v1.y);
        af[4 * kt + 2] = pk(v2.x, v2.y);
        af[4 * kt + 3] = pk(v3.x, v3.y);
    }
}
static __device__ __forceinline__ void load_af_bf16(const __nv_bfloat16* r0,
                                                    const __nv_bfloat16* r1,
                                                    int tg, uint32_t af[32]) {
    #pragma unroll
    for (int kt = 0; kt < 8; ++kt) {
        int c = kt * 16 + 2 * tg;
        af[4 * kt]     = *(const uint32_t*)(r0 + c);
        af[4 * kt + 1] = *(const uint32_t*)(r1 + c);
        af[4 * kt + 2] = *(const uint32_t*)(r0 + c + 8);
        af[4 * kt + 3] = *(const uint32_t*)(r1 + c + 8);
    }
}
static __device__ __forceinline__ void pack_gelu(const float acc[16][4],
                                                 const float* bias, int tg,
                                                 uint32_t af[32]) {
    #pragma unroll
    for (int kt = 0; kt < 8; ++kt) {
        int n0 = 2 * kt, n1 = 2 * kt + 1;
        float2 bA = *(const float2*)(bias + n0 * 8 + 2 * tg);
        float2 bB = *(const float2*)(bias + n1 * 8 + 2 * tg);
        af[4 * kt]     = pk(gelu_f(acc[n0][0] + bA.x), gelu_f(acc[n0][1] + bA.y));
        af[4 * kt + 1] = pk(gelu_f(acc[n0][2] + bA.x), gelu_f(acc[n0][3] + bA.y));
        af[4 * kt + 2] = pk(gelu_f(acc[n1][0] + bB.x), gelu_f(acc[n1][1] + bB.y));
        af[4 * kt + 3] = pk(gelu_f(acc[n1][2] + bB.x), gelu_f(acc[n1][3] + bB.y));
    }
}

// ================= kFoldT: biasA = b1 + hV @ W1[0:128]; zero g_dh =================
#define SFOLD (34816 + 512)
__global__ void __launch_bounds__(256, 1)
kFoldT(const float* __restrict__ x, const float* __restrict__ W,
       const float* __restrict__ b, float* __restrict__ out, int zdh) {
    extern __shared__ char sm[];
    __nv_bfloat16* Ws = (__nv_bfloat16*)sm;
    float* bsm = (float*)(sm + 34816);
    int tid = threadIdx.x, lane = tid & 31, warp = tid >> 5;
    int gid = lane >> 2, tg = lane & 3;
    load_w(W, Ws, 128, tid, 256);
    if (tid < 128) bsm[tid] = b[tid];
    __syncthreads();
    uint32_t loff = (uint32_t)(((lane & 15) * LDW + ((lane >> 4) * 8)) * 2);
    uint32_t wAddr = su32(Ws) + loff;
    for (int wt = blockIdx.x * 8 + warp; wt < NTILES; wt += gridDim.x * 8) {
        int r0 = wt * 16 + gid, r1 = r0 + 8;
        uint32_t af[32];
        float acc[16][4];
        load_af_f32(x + (size_t)r0 * 128, x + (size_t)r1 * 128, tg, af);
        zero16(acc);
        gemm_reg<8>(af, wAddr, acc);
        #pragma unroll
        for (int nt = 0; nt < 16; ++nt) {
            int c = nt * 8 + 2 * tg;
            float2 bb = *(const float2*)(bsm + c);
            *(float2*)(out + (size_t)r0 * 128 + c) = make_float2(acc[nt][0] + bb.x, acc[nt][1] + bb.y);
            *(float2*)(out + (size_t)r1 * 128 + c) = make_float2(acc[nt][2] + bb.x, acc[nt][3] + bb.y);
            if (zdh) {
                *(float2*)(g_dh + (size_t)r0 * 128 + c) = make_float2(0.f, 0.f);
                *(float2*)(g_dh + (size_t)r1 * 128 + c) = make_float2(0.f, 0.f);
            }
        }
    }
}

// ================= kEdge0: edge MLP1 + masked sum (512 thr, M=16, prefetch) ==========
#define KE0_SMEM (104448 + 1024)
__global__ void __launch_bounds__(512, 1)
kEdge0(const float* __restrict__ hE,
       const float* __restrict__ Wl1, const float* __restrict__ Wl2,
       const float* __restrict__ Wl3,
       const float* __restrict__ b2, const float* __restrict__ b3,
       const float* __restrict__ bias1, const float* __restrict__ matt) {
    extern __shared__ char sm[];
    float* bs = (float*)(sm + 104448);
    int tid = threadIdx.x, lane = tid & 31, warp = tid >> 5;
    int gid = lane >> 2, tg = lane & 3;

    load_w(Wl1, (__nv_bfloat16*)sm, 128, tid, 512);
    load_w(Wl2, (__nv_bfloat16*)(sm + 34816), 128, tid, 512);
    load_w(Wl3, (__nv_bfloat16*)(sm + 69632), 128, tid, 512);
    if (tid < 128) { bs[tid] = b2[tid]; bs[128 + tid] = b3[tid]; }
    __syncthreads();
    float* b2s = bs; float* b3s = bs + 128;

    uint32_t loff = (uint32_t)(((lane & 15) * LDW + ((lane >> 4) * 8)) * 2);
    uint32_t w1Addr = su32(sm) + loff;
    uint32_t w2Addr = w1Addr + 34816;
    uint32_t w3Addr = w2Addr + 34816;

    const int stride = gridDim.x * 16;
    int wt = blockIdx.x * 16 + warp;
    uint32_t af[32];
    float acc[16][4];
    if (wt < WTILES) {
        int r0 = wt * 16 + gid;
        load_af_f32(hE + (size_t)r0 * 128, hE + (size_t)(r0 + 8) * 128, tg, af);
    }
    while (wt < WTILES) {
        int rowbase = wt * 16;
        int r0 = rowbase + gid, r1 = r0 + 8;
        int node = rowbase / 48;
        zero16(acc);
        gemm_reg<8>(af, w1Addr, acc);
        pack_gelu(acc, bias1 + (size_t)node * 128, tg, af);
        zero16(acc);
        gemm_reg<8>(af, w2Addr, acc);
        pack_gelu(acc, b2s, tg, af);
        zero16(acc);
        gemm_reg<8>(af, w3Addr, acc);

        int wtn = wt + stride;
        if (wtn < WTILES) {
            int rn = wtn * 16 + gid;
            load_af_f32(hE + (size_t)rn * 128, hE + (size_t)(rn + 8) * 128, tg, af);
        }

        float m0 = __ldg(matt + r0), m1 = __ldg(matt + r1);
        #pragma unroll
        for (int nt = 0; nt < 16; ++nt) {
            float2 b = *(const float2*)(b3s + nt * 8 + 2 * tg);
            acc[nt][0] = (acc[nt][0] + b.x) * m0 + (acc[nt][2] + b.x) * m1;
            acc[nt][1] = (acc[nt][1] + b.y) * m0 + (acc[nt][3] + b.y) * m1;
        }
        #pragma unroll
        for (int o = 4; o < 32; o <<= 1)
            #pragma unroll
            for (int nt = 0; nt < 16; ++nt) {
                acc[nt][0] += __shfl_xor_sync(~0u, acc[nt][0], o);
                acc[nt][1] += __shfl_xor_sync(~0u, acc[nt][1], o);
            }
        if (lane < 4) {
            float* dst = g_dh + (size_t)node * 128;
            #pragma unroll
            for (int nt = 0; nt < 16; ++nt) {
                atomicAdd(dst + nt * 8 + 2 * lane,     acc[nt][0]);
                atomicAdd(dst + nt * 8 + 2 * lane + 1, acc[nt][1]);
            }
        }
        wt = wtn;
    }
}

// ===== kEdge1: edge MLP2 + LN3 (384 thr, dual prefetch: hE + gather both hidden) =====
#define KE1_SMEM (69632 + 34816 + 34816 + 2048)
__global__ void __launch_bounds__(384, 1)
kEdge1(const float* __restrict__ hE,
       const float* __restrict__ Wl1, const float* __restrict__ Wl2,
       const float* __restrict__ Wl3,
       const float* __restrict__ b2, const float* __restrict__ b3,
       const float* __restrict__ bias1, const int* __restrict__ Eidx,
       const float* __restrict__ g3, const float* __restrict__ bb3,
       float* __restrict__ outE) {
    extern __shared__ char sm[];
    float* bs = (float*)(sm + 69632 + 34816 + 34816);
    int tid = threadIdx.x, lane = tid & 31, warp = tid >> 5;
    int gid = lane >> 2, tg = lane & 3;

    load_w(Wl1, (__nv_bfloat16*)sm, 256, tid, 384);
    load_w(Wl2, (__nv_bfloat16*)(sm + 69632), 128, tid, 384);
    load_w(Wl3, (__nv_bfloat16*)(sm + 69632 + 34816), 128, tid, 384);
    if (tid < 128) {
        bs[tid] = b2[tid]; bs[128 + tid] = b3[tid];
        bs[256 + tid] = g3[tid]; bs[384 + tid] = bb3[tid];
    }
    __syncthreads();
    float* b2s = bs; float* b3s = bs + 128; float* g3s = bs + 256; float* bb3s = bs + 384;

    uint32_t loff = (uint32_t)(((lane & 15) * LDW + ((lane >> 4) * 8)) * 2);
    uint32_t w1Addr = su32(sm) + loff;
    uint32_t w2Addr = w1Addr + 69632;
    uint32_t w3Addr = w2Addr + 34816;

    const int stride = gridDim.x * 12;
    int wt = blockIdx.x * 12 + warp;
    uint32_t afE[32], afG[32];
    float acc[16][4];
    if (wt < WTILES) {   // prologue: current tile hE + gather
        int rb = wt * 16, r0 = rb + gid;
        load_af_f32(hE + (size_t)r0 * 128, hE + (size_t)(r0 + 8) * 128, tg, afE);
        int bbase = (rb / 98304) * 2048;
        int n0 = bbase + __ldg(Eidx + r0), n1 = bbase + __ldg(Eidx + r0 + 8);
        load_af_bf16(g_hvb + (size_t)n0 * 128, g_hvb + (size_t)n1 * 128, tg, afG);
    }
    while (wt < WTILES) {
        int rowbase = wt * 16;
        int r0 = rowbase + gid, r1 = r0 + 8;
        int node = rowbase / 48;
        zero16(acc);
        gemm_reg<8>(afE, w1Addr, acc);             // K chunk 1: hE
        gemm_reg<8>(afG, w1Addr + 128 * 272, acc); // K chunk 2: gathered h_V
        pack_gelu(acc, bias1 + (size_t)node * 128, tg, afE);

        int wtn = wt + stride;
        if (wtn < WTILES) {   // afG free: prefetch NEXT tile's gather now (~2 gemms ahead)
            int rbn = wtn * 16, rn = rbn + gid;
            int bbn = (rbn / 98304) * 2048;
            int n0 = bbn + __ldg(Eidx + rn), n1 = bbn + __ldg(Eidx + rn + 8);
            load_af_bf16(g_hvb + (size_t)n0 * 128, g_hvb + (size_t)n1 * 128, tg, afG);
        }

        zero16(acc);
        gemm_reg<8>(afE, w2Addr, acc);
        pack_gelu(acc, b2s, tg, afE);
        zero16(acc);
        gemm_reg<8>(afE, w3Addr, acc);

        if (wtn < WTILES) {   // afE free: prefetch next tile's hE during epilogue
            int rn = wtn * 16 + gid;
            load_af_f32(hE + (size_t)rn * 128, hE + (size_t)(rn + 8) * 128, tg, afE);
        }

        {   // LN3(hE + msg) -> outE  (hE rows are L1-resident from tile start)
            const float* e0 = hE + (size_t)r0 * 128;
            const float* e1 = hE + (size_t)r1 * 128;
            float sum0 = 0.f, sq0 = 0.f, sum1 = 0.f, sq1 = 0.f;
            #pragma unroll
            for (int nt = 0; nt < 16; ++nt) {
                int c = nt * 8 + 2 * tg;
                float2 b  = *(const float2*)(b3s + c);
                float2 h0 = *(const float2*)(e0 + c);
                float2 h1 = *(const float2*)(e1 + c);
                acc[nt][0] += b.x + h0.x; acc[nt][1] += b.y + h0.y;
                acc[nt][2] += b.x + h1.x; acc[nt][3] += b.y + h1.y;
                sum0 += acc[nt][0] + acc[nt][1];
                sq0  += acc[nt][0] * acc[nt][0] + acc[nt][1] * acc[nt][1];
                sum1 += acc[nt][2] + acc[nt][3];
                sq1  += acc[nt][2] * acc[nt][2] + acc[nt][3] * acc[nt][3];
            }
            #pragma unroll
            for (int o = 1; o < 4; o <<= 1) {
                sum0 += __shfl_xor_sync(~0u, sum0, o);
                sq0  += __shfl_xor_sync(~0u, sq0, o);
                sum1 += __shfl_xor_sync(~0u, sum1, o);
                sq1  += __shfl_xor_sync(~0u, sq1, o);
            }
            float mu0 = sum0 * (1.0f / 128.0f);
            float iv0 = rsqrtf(sq0 * (1.0f / 128.0f) - mu0 * mu0 + 1e-5f);
            float mu1 = sum1 * (1.0f / 128.0f);
            float iv1 = rsqrtf(sq1 * (1.0f / 128.0f) - mu1 * mu1 + 1e-5f);
            float* o0 = outE + (size_t)r0 * 128;
            float* o1 = outE + (size_t)r1 * 128;
            #pragma unroll
            for (int nt = 0; nt < 16; ++nt) {
                int c = nt * 8 + 2 * tg;
                float gx = g3s[c], gy = g3s[c + 1];
                float bx = bb3s[c], by = bb3s[c + 1];
                *(float2*)(o0 + c) = make_float2((acc[nt][0] - mu0) * iv0 * gx + bx,
                                                 (acc[nt][1] - mu0) * iv0 * gy + by);
                *(float2*)(o1 + c) = make_float2((acc[nt][2] - mu1) * iv1 * gx + bx,
                                                 (acc[nt][3] - mu1) * iv1 * gy + by);
            }
        }
        wt = wtn;
    }
}

// ============ kF1 (fused LN1): v1 = LN1(hV + dh/30); g_fb = gelu(v1 @ Win + bin) =====
#define SF1 (4 * 34816 + 2048 + 1024)
__global__ void __launch_bounds__(256, 1)
kF1(const float* __restrict__ hV, const float* __restrict__ Win,
    const float* __restrict__ bin, const float* __restrict__ g1,
    const float* __restrict__ bb1) {
    extern __shared__ char sm[];
    float* bin_s = (float*)(sm + 4 * 34816);
    float* g1s = bin_s + 512;
    float* b1s = g1s + 128;
    int tid = threadIdx.x, lane = tid & 31, warp = tid >> 5;
    int gid = lane >> 2, tg = lane & 3;
    for (int i = tid; i < 16384; i += 256) {
        float4 w = ((const float4*)Win)[i];
        int k = i >> 7, n = (i * 4) & 511;
        __nv_bfloat16* dst = (__nv_bfloat16*)(sm + (n >> 7) * 34816);
        int cc = n & 127;
        *(__nv_bfloat162*)(dst + k * LDW + cc)     = __floats2bfloat162_rn(w.x, w.y);
        *(__nv_bfloat162*)(dst + k * LDW + cc + 2) = __floats2bfloat162_rn(w.z, w.w);
    }
    for (int i = tid; i < 512; i += 256) bin_s[i] = bin[i];
    if (tid < 128) { g1s[tid] = g1[tid]; b1s[tid] = bb1[tid]; }
    __syncthreads();
    uint32_t loff = (uint32_t)(((lane & 15) * LDW + ((lane >> 4) * 8)) * 2);

    for (int wt = blockIdx.x * 8 + warp; wt < NTILES; wt += gridDim.x * 8) {
        int r0 = wt * 16 + gid, r1 = r0 + 8;
        const float* hv0 = hV + (size_t)r0 * 128;
        const float* hv1 = hV + (size_t)r1 * 128;
        const float* dh0 = g_dh + (size_t)r0 * 128;
        const float* dh1 = g_dh + (size_t)r1 * 128;
        float x0[32], x1[32];
        float sum0 = 0.f, sq0 = 0.f, sum1 = 0.f, sq1 = 0.f;
        #pragma unroll
        for (int j = 0; j < 16; ++j) {
            int c = (j >> 1) * 16 + (j & 1) * 8 + 2 * tg;
            float2 a0 = *(const float2*)(hv0 + c);
            float2 d0 = *(const float2*)(dh0 + c);
            float2 a1 = *(const float2*)(hv1 + c);
            float2 d1 = *(const float2*)(dh1 + c);
            x0[2 * j]     = a0.x + d0.x * (1.0f / 30.0f);
            x0[2 * j + 1] = a0.y + d0.y * (1.0f / 30.0f);
            x1[2 * j]     = a1.x + d1.x * (1.0f / 30.0f);
            x1[2 * j + 1] = a1.y + d1.y * (1.0f / 30.0f);
            sum0 += x0[2 * j] + x0[2 * j + 1];
            sq0  += x0[2 * j] * x0[2 * j] + x0[2 * j + 1] * x0[2 * j + 1];
            sum1 += x1[2 * j] + x1[2 * j + 1];
            sq1  += x1[2 * j] * x1[2 * j] + x1[2 * j + 1] * x1[2 * j + 1];
        }
        #pragma unroll
        for (int o = 1; o < 4; o <<= 1) {
            sum0 += __shfl_xor_sync(~0u, sum0, o);
            sq0  += __shfl_xor_sync(~0u, sq0, o);
            sum1 += __shfl_xor_sync(~0u, sum1, o);
            sq1  += __shfl_xor_sync(~0u, sq1, o);
        }
        float mu0 = sum0 * (1.0f / 128.0f);
        float iv0 = rsqrtf(sq0 * (1.0f / 128.0f) - mu0 * mu0 + 1e-5f);
        float mu1 = sum1 * (1.0f / 128.0f);
        float iv1 = rsqrtf(sq1 * (1.0f / 128.0f) - mu1 * mu1 + 1e-5f);
        uint32_t af[32];
        #pragma unroll
        for (int j = 0; j < 16; ++j) {
            int c = (j >> 1) * 16 + (j & 1) * 8 + 2 * tg;
            float y0a = (x0[2 * j] - mu0) * iv0 * g1s[c] + b1s[c];
            float y0b = (x0[2 * j + 1] - mu0) * iv0 * g1s[c + 1] + b1s[c + 1];
            float y1a = (x1[2 * j] - mu1) * iv1 * g1s[c] + b1s[c];
            float y1b = (x1[2 * j + 1] - mu1) * iv1 * g1s[c + 1] + b1s[c + 1];
            *(float2*)(g_v1 + (size_t)r0 * 128 + c) = make_float2(y0a, y0b);
            *(float2*)(g_v1 + (size_t)r1 * 128 + c) = make_float2(y1a, y1b);
            int kt = j >> 1, half = j & 1;
            af[4 * kt + 2 * half]     = pk(y0a, y0b);
            af[4 * kt + 2 * half + 1] = pk(y1a, y1b);
        }
        float acc[16][4];
        #pragma unroll
        for (int ng = 0; ng < 4; ++ng) {
            zero16(acc);
            gemm_reg<8>(af, su32(sm + ng * 34816) + loff, acc);
            #pragma unroll
            for (int nt = 0; nt < 16; ++nt) {
                int cg = ng * 128 + nt * 8 + 2 * tg;
                float2 b = *(const float2*)(bin_s + cg);
                *(uint32_t*)(g_fb + (size_t)r0 * 512 + cg) =
                    pk(gelu_f(acc[nt][0] + b.x), gelu_f(acc[nt][1] + b.y));
                *(uint32_t*)(g_fb + (size_t)r1 * 512 + cg) =
                    pk(gelu_f(acc[nt][2] + b.x), gelu_f(acc[nt][3] + b.y));
            }
        }
    }
}

// ==== kF2 (fused fold): outV = mask*LN2(v1 + fb@Wout + bout); biasC = b11 + outV@W11 ==
#define SF2 (139264 + 34816 + 2048)
__global__ void __launch_bounds__(256, 1)
kF2(const float* __restrict__ Wout, const float* __restrict__ bout,
    const float* __restrict__ g2, const float* __restrict__ bb2,
    const float* __restrict__ maskV, float* __restrict__ outV,
    const float* __restrict__ W11, const float* __restrict__ b11,
    float* __restrict__ biasC) {
    extern __shared__ char sm[];
    __nv_bfloat16* Ws = (__nv_bfloat16*)sm;
    __nv_bfloat16* W11s = (__nv_bfloat16*)(sm + 139264);
    float* bs = (float*)(sm + 139264 + 34816);
    int tid = threadIdx.x, lane = tid & 31, warp = tid >> 5;
    int gid = lane >> 2, tg = lane & 3;
    load_w(Wout, Ws, 512, tid, 256);
    load_w(W11, W11s, 128, tid, 256);
    if (tid < 128) { bs[tid] = bout[tid]; bs[128 + tid] = g2[tid];
                     bs[256 + tid] = bb2[tid]; bs[384 + tid] = b11[tid]; }
    __syncthreads();
    float* bo = bs; float* g2s = bs + 128; float* b2s = bs + 256; float* b11s = bs + 384;
    uint32_t loff = (uint32_t)(((lane & 15) * LDW + ((lane >> 4) * 8)) * 2);
    uint32_t wAddr = su32(Ws) + loff;
    uint32_t w11Addr = su32(W11s) + loff;

    for (int wt = blockIdx.x * 8 + warp; wt < NTILES; wt += gridDim.x * 8) {
        int r0 = wt * 16 + gid, r1 = r0 + 8;
        const __nv_bfloat16* f0 = g_fb + (size_t)r0 * 512;
        const __nv_bfloat16* f1 = g_fb + (size_t)r1 * 512;
        float acc[16][4];
        zero16(acc);
        #pragma unroll 4
        for (int kt = 0; kt < 32; ++kt) {
            uint32_t a[4];
            int c = kt * 16 + 2 * tg;
            a[0] = *(const uint32_t*)(f0 + c);
            a[1] = *(const uint32_t*)(f1 + c);
            a[2] = *(const uint32_t*)(f0 + c + 8);
            a[3] = *(const uint32_t*)(f1 + c + 8);
            #pragma unroll
            for (int nb = 0; nb < 8; ++nb) {
                uint32_t b[4];
                asm volatile("ldmatrix.sync.aligned.m8n8.x4.trans.shared.b16 {%0,%1,%2,%3},[%4];"
                             : "=r"(b[0]), "=r"(b[1]), "=r"(b[2]), "=r"(b[3])
                             : "r"(wAddr + kt * 4352 + nb * 32));
                MMA4(acc[2 * nb],     a, b[0], b[1]);
                MMA4(acc[2 * nb + 1], a, b[2], b[3]);
            }
        }
        const float* v0 = g_v1 + (size_t)r0 * 128;
        const float* v1 = g_v1 + (size_t)r1 * 128;
        float sum0 = 0.f, sq0 = 0.f, sum1 = 0.f, sq1 = 0.f;
        #pragma unroll
        for (int nt = 0; nt < 16; ++nt) {
            int c = nt * 8 + 2 * tg;
            float2 b  = *(const float2*)(bo + c);
            float2 h0 = *(const float2*)(v0 + c);
            float2 h1 = *(const float2*)(v1 + c);
            acc[nt][0] += b.x + h0.x; acc[nt][1] += b.y + h0.y;
            acc[nt][2] += b.x + h1.x; acc[nt][3] += b.y + h1.y;
            sum0 += acc[nt][0] + acc[nt][1];
            sq0  += acc[nt][0] * acc[nt][0] + acc[nt][1] * acc[nt][1];
            sum1 += acc[nt][2] + acc[nt][3];
            sq1  += acc[nt][2] * acc[nt][2] + acc[nt][3] * acc[nt][3];
        }
        #pragma unroll
        for (int o = 1; o < 4; o <<= 1) {
            sum0 += __shfl_xor_sync(~0u, sum0, o);
            sq0  += __shfl_xor_sync(~0u, sq0, o);
            sum1 += __shfl_xor_sync(~0u, sum1, o);
            sq1  += __shfl_xor_sync(~0u, sq1, o);
        }
        float mu0 = sum0 * (1.0f / 128.0f);
        float iv0 = rsqrtf(sq0 * (1.0f / 128.0f) - mu0 * mu0 + 1e-5f);
        float mu1 = sum1 * (1.0f / 128.0f);
        float iv1 = rsqrtf(sq1 * (1.0f / 128.0f) - mu1 * mu1 + 1e-5f);
        float mv0 = __ldg(maskV + r0), mv1 = __ldg(maskV + r1);
        uint32_t af[32];
        #pragma unroll
        for (int nt = 0; nt < 16; ++nt) {
            int c = nt * 8 + 2 * tg;
            float gx = g2s[c], gy = g2s[c + 1], bx = b2s[c], by = b2s[c + 1];
            float2 y0 = { ((acc[nt][0] - mu0) * iv0 * gx + bx) * mv0,
                          ((acc[nt][1] - mu0) * iv0 * gy + by) * mv0 };
            float2 y1 = { ((acc[nt][2] - mu1) * iv1 * gx + bx) * mv1,
                          ((acc[nt][3] - mu1) * iv1 * gy + by) * mv1 };
            *(float2*)(outV + (size_t)r0 * 128 + c) = y0;
            *(float2*)(outV + (size_t)r1 * 128 + c) = y1;
            uint32_t p0 = pk(y0.x, y0.y), p1 = pk(y1.x, y1.y);
            *(uint32_t*)(g_hvb + (size_t)r0 * 128 + c) = p0;
            *(uint32_t*)(g_hvb + (size_t)r1 * 128 + c) = p1;
            int kt = nt >> 1, half = nt & 1;
            af[4 * kt + 2 * half]     = p0;
            af[4 * kt + 2 * half + 1] = p1;
        }
        zero16(acc);
        gemm_reg<8>(af, w11Addr, acc);
        #pragma unroll
        for (int nt = 0; nt < 16; ++nt) {
            int c = nt * 8 + 2 * tg;
            float2 bb = *(const float2*)(b11s + c);
            *(float2*)(biasC + (size_t)r0 * 128 + c) = make_float2(acc[nt][0] + bb.x, acc[nt][1] + bb.y);
            *(float2*)(biasC + (size_t)r1 * 128 + c) = make_float2(acc[nt][2] + bb.x, acc[nt][3] + bb.y);
        }
    }
}

extern "C" void kernel_launch(void* const* d_in, const int* in_sizes, int n_in,
                              void* d_out, int out_size) {
    const float* hV = (const float*)d_in[0];
    const float* hE = (const float*)d_in[1];
    const float* mV = (const float*)d_in[2];
    const int* Eidx = (const int*)d_in[3];
    const float* matt = (const float*)d_in[4];
    const float* W1 = (const float*)d_in[5],  *b1 = (const float*)d_in[6];
    const float* W2 = (const float*)d_in[7],  *b2 = (const float*)d_in[8];
    const float* W3 = (const float*)d_in[9],  *b3 = (const float*)d_in[10];
    const float* W11 = (const float*)d_in[11], *b11 = (const float*)d_in[12];
    const float* W12 = (const float*)d_in[13], *b12 = (const float*)d_in[14];
    const float* W13 = (const float*)d_in[15], *b13 = (const float*)d_in[16];
    const float* Win = (const float*)d_in[17], *bin = (const float*)d_in[18];
    const float* Wout = (const float*)d_in[19], *bout = (const float*)d_in[20];
    const float* g1 = (const float*)d_in[21], *bb1 = (const float*)d_in[22];
    const float* g2 = (const float*)d_in[23], *bb2 = (const float*)d_in[24];
    const float* g3 = (const float*)d_in[25], *bb3 = (const float*)d_in[26];
    float* outV = (float*)d_out;
    float* outE = (float*)d_out + HV_ELEMS;
    float* biasA; cudaGetSymbolAddress((void**)&biasA, g_biasA);
    float* biasC; cudaGetSymbolAddress((void**)&biasC, g_biasC);

    cudaFuncSetAttribute(kFoldT, cudaFuncAttributeMaxDynamicSharedMemorySize, SFOLD);
    cudaFuncSetAttribute(kEdge0, cudaFuncAttributeMaxDynamicSharedMemorySize, KE0_SMEM);
    cudaFuncSetAttribute(kEdge1, cudaFuncAttributeMaxDynamicSharedMemorySize, KE1_SMEM);
    cudaFuncSetAttribute(kF1, cudaFuncAttributeMaxDynamicSharedMemorySize, SF1);
    cudaFuncSetAttribute(kF2, cudaFuncAttributeMaxDynamicSharedMemorySize, SF2);

    kFoldT<<<64, 256, SFOLD>>>(hV, W1, b1, biasA, 1);
    kEdge0<<<148, 512, KE0_SMEM>>>(hE, W1 + 128 * 128, W2, W3, b2, b3, biasA, matt);
    kF1<<<64, 256, SF1>>>(hV, Win, bin, g1, bb1);
    kF2<<<64, 256, SF2>>>(Wout, bout, g2, bb2, mV, outV, W11, b11, biasC);
    kEdge1<<<148, 384, KE1_SMEM>>>(hE, W11 + 128 * 128, W12, W13, b12, b13,
                                   biasC, Eidx, g3, bb3, outE);
}

// round 15
// speedup vs baseline: 1.1897x; 1.0480x over previous
#include <cuda_runtime.h>
#include <cuda_bf16.h>
#include <cstdint>

#define NODES 8192
#define H_ 128
#define K_ 48
#define EDGES (NODES * K_)
#define WTILES (EDGES / 16)
#define NTILES (NODES / 16)
#define HV_ELEMS (NODES * H_)
#define LDW 136

// g_wb row offsets (136-elem rows, bf16, smem-ready layout)
#define WB_W1   0
#define WB_W2   256
#define WB_W3   384
#define WB_W11  512
#define WB_W12  896
#define WB_W13  1024
#define WB_WIN  1152
#define WB_WOUT 1664
#define WB_ROWS 2176

__device__ __align__(16) float         g_v1[NODES * H_];
__device__ __align__(16) __nv_bfloat16 g_fb[NODES * 512];
__device__ __align__(16) __nv_bfloat16 g_hvb[NODES * H_];
__device__ __align__(16) float         g_dh[NODES * H_];
__device__ __align__(16) float         g_biasA[NODES * H_];
__device__ __align__(16) float         g_biasC[NODES * H_];
__device__ __align__(16) __nv_bfloat16 g_wb[WB_ROWS * LDW];

static __device__ __forceinline__ unsigned su32(const void* p) {
    return (unsigned)__cvta_generic_to_shared(p);
}
static __device__ __forceinline__ float gelu_f(float x) {
    float u = 0.7978845608028654f * (x + 0.044715f * x * x * x), t;
    asm("tanh.approx.f32 %0, %1;" : "=f"(t) : "f"(u));
    return 0.5f * x * (1.0f + t);
}
static __device__ __forceinline__ uint32_t pk(float x, float y) {
    __nv_bfloat162 h = __floats2bfloat162_rn(x, y);
    return *(uint32_t*)&h;
}
// contiguous smem-ready weight copy: n16 uint4 elements
static __device__ __forceinline__ void copy_wb(int rowoff, void* dstsm, int rows,
                                               int tid, int nthr) {
    const uint4* src = (const uint4*)(g_wb + (size_t)rowoff * LDW);
    uint4* dst = (uint4*)dstsm;
    int n16 = rows * 17;   // 136 bf16 = 272B = 17 uint4 per row
    for (int i = tid; i < n16; i += nthr) dst[i] = src[i];
}

#define MMA4(ac, a, b0, b1) \
    asm volatile("mma.sync.aligned.m16n8k16.row.col.f32.bf16.bf16.f32 " \
                 "{%0,%1,%2,%3},{%4,%5,%6,%7},{%8,%9},{%0,%1,%2,%3};" \
                 : "+f"((ac)[0]), "+f"((ac)[1]), "+f"((ac)[2]), "+f"((ac)[3]) \
                 : "r"((a)[0]), "r"((a)[1]), "r"((a)[2]), "r"((a)[3]), \
                   "r"(b0), "r"(b1))

static __device__ __forceinline__ void zero16(float acc[16][4]) {
    #pragma unroll
    for (int i = 0; i < 16; ++i)
        #pragma unroll
        for (int j = 0; j < 4; ++j) acc[i][j] = 0.0f;
}

template <int NKT>
static __device__ __forceinline__ void gemm_reg(const uint32_t* af, uint32_t wAddr,
                                                float acc[16][4]) {
    #pragma unroll
    for (int kt = 0; kt < NKT; ++kt) {
        #pragma unroll
        for (int nb = 0; nb < 8; ++nb) {
            uint32_t b[4];
            asm volatile("ldmatrix.sync.aligned.m8n8.x4.trans.shared.b16 {%0,%1,%2,%3},[%4];"
                         : "=r"(b[0]), "=r"(b[1]), "=r"(b[2]), "=r"(b[3])
                         : "r"(wAddr + kt * 4352 + nb * 32));
            MMA4(acc[2 * nb],     af + 4 * kt, b[0], b[1]);
            MMA4(acc[2 * nb + 1], af + 4 * kt, b[2], b[3]);
        }
    }
}

static __device__ __forceinline__ void load_af_f32(const float* r0, const float* r1,
                                                   int tg, uint32_t af[32]) {
    #pragma unroll
    for (int kt = 0; kt < 8; ++kt) {
        int c = kt * 16 + 2 * tg;
        float2 v0 = *(const float2*)(r0 + c);
        float2 v1 = *(const float2*)(r1 + c);
        float2 v2 = *(const float2*)(r0 + c + 8);
        float2 v3 = *(const float2*)(r1 + c + 8);
        af[4 * kt]     = pk(v0.x, v0.y);
        af[4 * kt + 1] = pk(v1.x, v1.y);
        af[4 * kt + 2] = pk(v2.x, v2.y);
        af[4 * kt + 3] = pk(v3.x, v3.y);
    }
}
static __device__ __forceinline__ void load_af_bf16(const __nv_bfloat16* r0,
                                                    const __nv_bfloat16* r1,
                                                    int tg, uint32_t af[32]) {
    #pragma unroll
    for (int kt = 0; kt < 8; ++kt) {
        int c = kt * 16 + 2 * tg;
        af[4 * kt]     = *(const uint32_t*)(r0 + c);
        af[4 * kt + 1] = *(const uint32_t*)(r1 + c);
        af[4 * kt + 2] = *(const uint32_t*)(r0 + c + 8);
        af[4 * kt + 3] = *(const uint32_t*)(r1 + c + 8);
    }
}
static __device__ __forceinline__ void pack_gelu(const float acc[16][4],
                                                 const float* bias, int tg,
                                                 uint32_t af[32]) {
    #pragma unroll
    for (int kt = 0; kt < 8; ++kt) {
        int n0 = 2 * kt, n1 = 2 * kt + 1;
        float2 bA = *(const float2*)(bias + n0 * 8 + 2 * tg);
        float2 bB = *(const float2*)(bias + n1 * 8 + 2 * tg);
        af[4 * kt]     = pk(gelu_f(acc[n0][0] + bA.x), gelu_f(acc[n0][1] + bA.y));
        af[4 * kt + 1] = pk(gelu_f(acc[n0][2] + bA.x), gelu_f(acc[n0][3] + bA.y));
        af[4 * kt + 2] = pk(gelu_f(acc[n1][0] + bB.x), gelu_f(acc[n1][1] + bB.y));
        af[4 * kt + 3] = pk(gelu_f(acc[n1][2] + bB.x), gelu_f(acc[n1][3] + bB.y));
    }
}

// ========= kPrep: one-shot fp32 -> bf16 weight conversion into smem-ready layout =====
__global__ void __launch_bounds__(256)
kPrep(const float* __restrict__ W1, const float* __restrict__ W2,
      const float* __restrict__ W3, const float* __restrict__ W11,
      const float* __restrict__ W12, const float* __restrict__ W13,
      const float* __restrict__ Win, const float* __restrict__ Wout) {
    int total = WB_ROWS * 64;   // bf162 pairs
    for (int i = blockIdx.x * 256 + threadIdx.x; i < total; i += gridDim.x * 256) {
        int r = i >> 6, c2 = (i & 63) * 2;
        const float* s; int off;
        if (r < 256)       { s = W1;  off = r * 128; }
        else if (r < 384)  { s = W2;  off = (r - 256) * 128; }
        else if (r < 512)  { s = W3;  off = (r - 384) * 128; }
        else if (r < 896)  { s = W11; off = (r - 512) * 128; }
        else if (r < 1024) { s = W12; off = (r - 896) * 128; }
        else if (r < 1152) { s = W13; off = (r - 1024) * 128; }
        else if (r < 1664) { int l = r - 1152; s = Win; off = (l & 127) * 512 + (l >> 7) * 128; }
        else               { s = Wout; off = (r - 1664) * 128; }
        float2 v = *(const float2*)(s + off + c2);
        *(__nv_bfloat162*)(g_wb + (size_t)r * LDW + c2) = __floats2bfloat162_rn(v.x, v.y);
    }
}

// ================= kFoldT: biasA = b1 + hV @ W1[0:128]; zero g_dh =================
#define SFOLD (34816 + 512)
__global__ void __launch_bounds__(128, 1)
kFoldT(const float* __restrict__ x, const float* __restrict__ b,
       float* __restrict__ out, int zdh) {
    extern __shared__ char sm[];
    float* bsm = (float*)(sm + 34816);
    int tid = threadIdx.x, lane = tid & 31, warp = tid >> 5;
    int gid = lane >> 2, tg = lane & 3;
    copy_wb(WB_W1, sm, 128, tid, 128);
    if (tid < 128) bsm[tid] = b[tid];
    __syncthreads();
    uint32_t loff = (uint32_t)(((lane & 15) * LDW + ((lane >> 4) * 8)) * 2);
    uint32_t wAddr = su32(sm) + loff;
    for (int wt = blockIdx.x * 4 + warp; wt < NTILES; wt += gridDim.x * 4) {
        int r0 = wt * 16 + gid, r1 = r0 + 8;
        uint32_t af[32];
        float acc[16][4];
        load_af_f32(x + (size_t)r0 * 128, x + (size_t)r1 * 128, tg, af);
        zero16(acc);
        gemm_reg<8>(af, wAddr, acc);
        #pragma unroll
        for (int nt = 0; nt < 16; ++nt) {
            int c = nt * 8 + 2 * tg;
            float2 bb = *(const float2*)(bsm + c);
            *(float2*)(out + (size_t)r0 * 128 + c) = make_float2(acc[nt][0] + bb.x, acc[nt][1] + bb.y);
            *(float2*)(out + (size_t)r1 * 128 + c) = make_float2(acc[nt][2] + bb.x, acc[nt][3] + bb.y);
            if (zdh) {
                *(float2*)(g_dh + (size_t)r0 * 128 + c) = make_float2(0.f, 0.f);
                *(float2*)(g_dh + (size_t)r1 * 128 + c) = make_float2(0.f, 0.f);
            }
        }
    }
}

// ================= kEdge0: edge MLP1 + masked sum (512 thr, prefetch) ==========
#define KE0_SMEM (104448 + 1024)
__global__ void __launch_bounds__(512, 1)
kEdge0(const float* __restrict__ hE,
       const float* __restrict__ b2, const float* __restrict__ b3,
       const float* __restrict__ bias1, const float* __restrict__ matt) {
    extern __shared__ char sm[];
    float* bs = (float*)(sm + 104448);
    int tid = threadIdx.x, lane = tid & 31, warp = tid >> 5;
    int gid = lane >> 2, tg = lane & 3;

    copy_wb(WB_W1 + 128, sm, 384, tid, 512);   // W1[128:256] | W2 | W3 contiguous
    if (tid < 128) { bs[tid] = b2[tid]; bs[128 + tid] = b3[tid]; }
    __syncthreads();
    float* b2s = bs; float* b3s = bs + 128;

    uint32_t loff = (uint32_t)(((lane & 15) * LDW + ((lane >> 4) * 8)) * 2);
    uint32_t w1Addr = su32(sm) + loff;
    uint32_t w2Addr = w1Addr + 34816;
    uint32_t w3Addr = w2Addr + 34816;

    const int stride = gridDim.x * 16;
    int wt = blockIdx.x * 16 + warp;
    uint32_t af[32];
    float acc[16][4];
    if (wt < WTILES) {
        int r0 = wt * 16 + gid;
        load_af_f32(hE + (size_t)r0 * 128, hE + (size_t)(r0 + 8) * 128, tg, af);
    }
    while (wt < WTILES) {
        int rowbase = wt * 16;
        int r0 = rowbase + gid, r1 = r0 + 8;
        int node = rowbase / 48;
        zero16(acc);
        gemm_reg<8>(af, w1Addr, acc);
        pack_gelu(acc, bias1 + (size_t)node * 128, tg, af);
        zero16(acc);
        gemm_reg<8>(af, w2Addr, acc);
        pack_gelu(acc, b2s, tg, af);
        zero16(acc);
        gemm_reg<8>(af, w3Addr, acc);

        int wtn = wt + stride;
        if (wtn < WTILES) {
            int rn = wtn * 16 + gid;
            load_af_f32(hE + (size_t)rn * 128, hE + (size_t)(rn + 8) * 128, tg, af);
        }

        float m0 = __ldg(matt + r0), m1 = __ldg(matt + r1);
        #pragma unroll
        for (int nt = 0; nt < 16; ++nt) {
            float2 b = *(const float2*)(b3s + nt * 8 + 2 * tg);
            acc[nt][0] = (acc[nt][0] + b.x) * m0 + (acc[nt][2] + b.x) * m1;
            acc[nt][1] = (acc[nt][1] + b.y) * m0 + (acc[nt][3] + b.y) * m1;
        }
        #pragma unroll
        for (int o = 4; o < 32; o <<= 1)
            #pragma unroll
            for (int nt = 0; nt < 16; ++nt) {
                acc[nt][0] += __shfl_xor_sync(~0u, acc[nt][0], o);
                acc[nt][1] += __shfl_xor_sync(~0u, acc[nt][1], o);
            }
        if (lane < 4) {
            float* dst = g_dh + (size_t)node * 128;
            #pragma unroll
            for (int nt = 0; nt < 16; ++nt) {
                atomicAdd(dst + nt * 8 + 2 * lane,     acc[nt][0]);
                atomicAdd(dst + nt * 8 + 2 * lane + 1, acc[nt][1]);
            }
        }
        wt = wtn;
    }
}

// ===== kEdge1: edge MLP2 + LN3 (384 thr, dual prefetch) =====
#define KE1_SMEM (139264 + 2048)
__global__ void __launch_bounds__(384, 1)
kEdge1(const float* __restrict__ hE,
       const float* __restrict__ b2, const float* __restrict__ b3,
       const float* __restrict__ bias1, const int* __restrict__ Eidx,
       const float* __restrict__ g3, const float* __restrict__ bb3,
       float* __restrict__ outE) {
    extern __shared__ char sm[];
    float* bs = (float*)(sm + 139264);
    int tid = threadIdx.x, lane = tid & 31, warp = tid >> 5;
    int gid = lane >> 2, tg = lane & 3;

    copy_wb(WB_W11 + 128, sm, 512, tid, 384);  // W11[128:384] | W12 | W13 contiguous
    if (tid < 128) {
        bs[tid] = b2[tid]; bs[128 + tid] = b3[tid];
        bs[256 + tid] = g3[tid]; bs[384 + tid] = bb3[tid];
    }
    __syncthreads();
    float* b2s = bs; float* b3s = bs + 128; float* g3s = bs + 256; float* bb3s = bs + 384;

    uint32_t loff = (uint32_t)(((lane & 15) * LDW + ((lane >> 4) * 8)) * 2);
    uint32_t w1Addr = su32(sm) + loff;
    uint32_t w2Addr = w1Addr + 69632;
    uint32_t w3Addr = w2Addr + 34816;

    const int stride = gridDim.x * 12;
    int wt = blockIdx.x * 12 + warp;
    uint32_t afE[32], afG[32];
    float acc[16][4];
    if (wt < WTILES) {
        int rb = wt * 16, r0 = rb + gid;
        load_af_f32(hE + (size_t)r0 * 128, hE + (size_t)(r0 + 8) * 128, tg, afE);
        int bbase = (rb / 98304) * 2048;
        int n0 = bbase + __ldg(Eidx + r0), n1 = bbase + __ldg(Eidx + r0 + 8);
        load_af_bf16(g_hvb + (size_t)n0 * 128, g_hvb + (size_t)n1 * 128, tg, afG);
    }
    while (wt < WTILES) {
        int rowbase = wt * 16;
        int r0 = rowbase + gid, r1 = r0 + 8;
        int node = rowbase / 48;
        zero16(acc);
        gemm_reg<8>(afE, w1Addr, acc);
        gemm_reg<8>(afG, w1Addr + 128 * 272, acc);
        pack_gelu(acc, bias1 + (size_t)node * 128, tg, afE);

        int wtn = wt + stride;
        if (wtn < WTILES) {
            int rbn = wtn * 16, rn = rbn + gid;
            int bbn = (rbn / 98304) * 2048;
            int n0 = bbn + __ldg(Eidx + rn), n1 = bbn + __ldg(Eidx + rn + 8);
            load_af_bf16(g_hvb + (size_t)n0 * 128, g_hvb + (size_t)n1 * 128, tg, afG);
        }

        zero16(acc);
        gemm_reg<8>(afE, w2Addr, acc);
        pack_gelu(acc, b2s, tg, afE);
        zero16(acc);
        gemm_reg<8>(afE, w3Addr, acc);

        if (wtn < WTILES) {
            int rn = wtn * 16 + gid;
            load_af_f32(hE + (size_t)rn * 128, hE + (size_t)(rn + 8) * 128, tg, afE);
        }

        {
            const float* e0 = hE + (size_t)r0 * 128;
            const float* e1 = hE + (size_t)r1 * 128;
            float sum0 = 0.f, sq0 = 0.f, sum1 = 0.f, sq1 = 0.f;
            #pragma unroll
            for (int nt = 0; nt < 16; ++nt) {
                int c = nt * 8 + 2 * tg;
                float2 b  = *(const float2*)(b3s + c);
                float2 h0 = *(const float2*)(e0 + c);
                float2 h1 = *(const float2*)(e1 + c);
                acc[nt][0] += b.x + h0.x; acc[nt][1] += b.y + h0.y;
                acc[nt][2] += b.x + h1.x; acc[nt][3] += b.y + h1.y;
                sum0 += acc[nt][0] + acc[nt][1];
                sq0  += acc[nt][0] * acc[nt][0] + acc[nt][1] * acc[nt][1];
                sum1 += acc[nt][2] + acc[nt][3];
                sq1  += acc[nt][2] * acc[nt][2] + acc[nt][3] * acc[nt][3];
            }
            #pragma unroll
            for (int o = 1; o < 4; o <<= 1) {
                sum0 += __shfl_xor_sync(~0u, sum0, o);
                sq0  += __shfl_xor_sync(~0u, sq0, o);
                sum1 += __shfl_xor_sync(~0u, sum1, o);
                sq1  += __shfl_xor_sync(~0u, sq1, o);
            }
            float mu0 = sum0 * (1.0f / 128.0f);
            float iv0 = rsqrtf(sq0 * (1.0f / 128.0f) - mu0 * mu0 + 1e-5f);
            float mu1 = sum1 * (1.0f / 128.0f);
            float iv1 = rsqrtf(sq1 * (1.0f / 128.0f) - mu1 * mu1 + 1e-5f);
            float* o0 = outE + (size_t)r0 * 128;
            float* o1 = outE + (size_t)r1 * 128;
            #pragma unroll
            for (int nt = 0; nt < 16; ++nt) {
                int c = nt * 8 + 2 * tg;
                float gx = g3s[c], gy = g3s[c + 1];
                float bx = bb3s[c], by = bb3s[c + 1];
                *(float2*)(o0 + c) = make_float2((acc[nt][0] - mu0) * iv0 * gx + bx,
                                                 (acc[nt][1] - mu0) * iv0 * gy + by);
                *(float2*)(o1 + c) = make_float2((acc[nt][2] - mu1) * iv1 * gx + bx,
                                                 (acc[nt][3] - mu1) * iv1 * gy + by);
            }
        }
        wt = wtn;
    }
}

// ============ kF1 (fused LN1): v1 = LN1(hV + dh/30); g_fb = gelu(v1 @ Win + bin) =====
#define SF1 (4 * 34816 + 2048 + 1024)
__global__ void __launch_bounds__(128, 1)
kF1(const float* __restrict__ hV, const float* __restrict__ bin,
    const float* __restrict__ g1, const float* __restrict__ bb1) {
    extern __shared__ char sm[];
    float* bin_s = (float*)(sm + 4 * 34816);
    float* g1s = bin_s + 512;
    float* b1s = g1s + 128;
    int tid = threadIdx.x, lane = tid & 31, warp = tid >> 5;
    int gid = lane >> 2, tg = lane & 3;
    copy_wb(WB_WIN, sm, 512, tid, 128);
    for (int i = tid; i < 512; i += 128) bin_s[i] = bin[i];
    if (tid < 128) { g1s[tid] = g1[tid]; b1s[tid] = bb1[tid]; }
    __syncthreads();
    uint32_t loff = (uint32_t)(((lane & 15) * LDW + ((lane >> 4) * 8)) * 2);

    for (int wt = blockIdx.x * 4 + warp; wt < NTILES; wt += gridDim.x * 4) {
        int r0 = wt * 16 + gid, r1 = r0 + 8;
        const float* hv0 = hV + (size_t)r0 * 128;
        const float* hv1 = hV + (size_t)r1 * 128;
        const float* dh0 = g_dh + (size_t)r0 * 128;
        const float* dh1 = g_dh + (size_t)r1 * 128;
        float x0[32], x1[32];
        float sum0 = 0.f, sq0 = 0.f, sum1 = 0.f, sq1 = 0.f;
        #pragma unroll
        for (int j = 0; j < 16; ++j) {
            int c = (j >> 1) * 16 + (j & 1) * 8 + 2 * tg;
            float2 a0 = *(const float2*)(hv0 + c);
            float2 d0 = *(const float2*)(dh0 + c);
            float2 a1 = *(const float2*)(hv1 + c);
            float2 d1 = *(const float2*)(dh1 + c);
            x0[2 * j]     = a0.x + d0.x * (1.0f / 30.0f);
            x0[2 * j + 1] = a0.y + d0.y * (1.0f / 30.0f);
            x1[2 * j]     = a1.x + d1.x * (1.0f / 30.0f);
            x1[2 * j + 1] = a1.y + d1.y * (1.0f / 30.0f);
            sum0 += x0[2 * j] + x0[2 * j + 1];
            sq0  += x0[2 * j] * x0[2 * j] + x0[2 * j + 1] * x0[2 * j + 1];
            sum1 += x1[2 * j] + x1[2 * j + 1];
            sq1  += x1[2 * j] * x1[2 * j] + x1[2 * j + 1] * x1[2 * j + 1];
        }
        #pragma unroll
        for (int o = 1; o < 4; o <<= 1) {
            sum0 += __shfl_xor_sync(~0u, sum0, o);
            sq0  += __shfl_xor_sync(~0u, sq0, o);
            sum1 += __shfl_xor_sync(~0u, sum1, o);
            sq1  += __shfl_xor_sync(~0u, sq1, o);
        }
        float mu0 = sum0 * (1.0f / 128.0f);
        float iv0 = rsqrtf(sq0 * (1.0f / 128.0f) - mu0 * mu0 + 1e-5f);
        float mu1 = sum1 * (1.0f / 128.0f);
        float iv1 = rsqrtf(sq1 * (1.0f / 128.0f) - mu1 * mu1 + 1e-5f);
        uint32_t af[32];
        #pragma unroll
        for (int j = 0; j < 16; ++j) {
            int c = (j >> 1) * 16 + (j & 1) * 8 + 2 * tg;
            float y0a = (x0[2 * j] - mu0) * iv0 * g1s[c] + b1s[c];
            float y0b = (x0[2 * j + 1] - mu0) * iv0 * g1s[c + 1] + b1s[c + 1];
            float y1a = (x1[2 * j] - mu1) * iv1 * g1s[c] + b1s[c];
            float y1b = (x1[2 * j + 1] - mu1) * iv1 * g1s[c + 1] + b1s[c + 1];
            *(float2*)(g_v1 + (size_t)r0 * 128 + c) = make_float2(y0a, y0b);
            *(float2*)(g_v1 + (size_t)r1 * 128 + c) = make_float2(y1a, y1b);
            int kt = j >> 1, half = j & 1;
            af[4 * kt + 2 * half]     = pk(y0a, y0b);
            af[4 * kt + 2 * half + 1] = pk(y1a, y1b);
        }
        float acc[16][4];
        #pragma unroll
        for (int ng = 0; ng < 4; ++ng) {
            zero16(acc);
            gemm_reg<8>(af, su32(sm + ng * 34816) + loff, acc);
            #pragma unroll
            for (int nt = 0; nt < 16; ++nt) {
                int cg = ng * 128 + nt * 8 + 2 * tg;
                float2 b = *(const float2*)(bin_s + cg);
                *(uint32_t*)(g_fb + (size_t)r0 * 512 + cg) =
                    pk(gelu_f(acc[nt][0] + b.x), gelu_f(acc[nt][1] + b.y));
                *(uint32_t*)(g_fb + (size_t)r1 * 512 + cg) =
                    pk(gelu_f(acc[nt][2] + b.x), gelu_f(acc[nt][3] + b.y));
            }
        }
    }
}

// ==== kF2 (fused fold): outV = mask*LN2(v1 + fb@Wout + bout); biasC = b11 + outV@W11 ==
#define SF2 (139264 + 34816 + 2048)
__global__ void __launch_bounds__(128, 1)
kF2(const float* __restrict__ bout, const float* __restrict__ g2,
    const float* __restrict__ bb2, const float* __restrict__ maskV,
    float* __restrict__ outV, const float* __restrict__ b11,
    float* __restrict__ biasC) {
    extern __shared__ char sm[];
    float* bs = (float*)(sm + 139264 + 34816);
    int tid = threadIdx.x, lane = tid & 31, warp = tid >> 5;
    int gid = lane >> 2, tg = lane & 3;
    copy_wb(WB_WOUT, sm, 512, tid, 128);
    copy_wb(WB_W11, sm + 139264, 128, tid, 128);
    if (tid < 128) { bs[tid] = bout[tid]; bs[128 + tid] = g2[tid];
                     bs[256 + tid] = bb2[tid]; bs[384 + tid] = b11[tid]; }
    __syncthreads();
    float* bo = bs; float* g2s = bs + 128; float* b2s = bs + 256; float* b11s = bs + 384;
    uint32_t loff = (uint32_t)(((lane & 15) * LDW + ((lane >> 4) * 8)) * 2);
    uint32_t wAddr = su32(sm) + loff;
    uint32_t w11Addr = wAddr + 139264;

    for (int wt = blockIdx.x * 4 + warp; wt < NTILES; wt += gridDim.x * 4) {
        int r0 = wt * 16 + gid, r1 = r0 + 8;
        const __nv_bfloat16* f0 = g_fb + (size_t)r0 * 512;
        const __nv_bfloat16* f1 = g_fb + (size_t)r1 * 512;
        float acc[16][4];
        zero16(acc);
        #pragma unroll 4
        for (int kt = 0; kt < 32; ++kt) {
            uint32_t a[4];
            int c = kt * 16 + 2 * tg;
            a[0] = *(const uint32_t*)(f0 + c);
            a[1] = *(const uint32_t*)(f1 + c);
            a[2] = *(const uint32_t*)(f0 + c + 8);
            a[3] = *(const uint32_t*)(f1 + c + 8);
            #pragma unroll
            for (int nb = 0; nb < 8; ++nb) {
                uint32_t b[4];
                asm volatile("ldmatrix.sync.aligned.m8n8.x4.trans.shared.b16 {%0,%1,%2,%3},[%4];"
                             : "=r"(b[0]), "=r"(b[1]), "=r"(b[2]), "=r"(b[3])
                             : "r"(wAddr + kt * 4352 + nb * 32));
                MMA4(acc[2 * nb],     a, b[0], b[1]);
                MMA4(acc[2 * nb + 1], a, b[2], b[3]);
            }
        }
        const float* v0 = g_v1 + (size_t)r0 * 128;
        const float* v1 = g_v1 + (size_t)r1 * 128;
        float sum0 = 0.f, sq0 = 0.f, sum1 = 0.f, sq1 = 0.f;
        #pragma unroll
        for (int nt = 0; nt < 16; ++nt) {
            int c = nt * 8 + 2 * tg;
            float2 b  = *(const float2*)(bo + c);
            float2 h0 = *(const float2*)(v0 + c);
            float2 h1 = *(const float2*)(v1 + c);
            acc[nt][0] += b.x + h0.x; acc[nt][1] += b.y + h0.y;
            acc[nt][2] += b.x + h1.x; acc[nt][3] += b.y + h1.y;
            sum0 += acc[nt][0] + acc[nt][1];
            sq0  += acc[nt][0] * acc[nt][0] + acc[nt][1] * acc[nt][1];
            sum1 += acc[nt][2] + acc[nt][3];
            sq1  += acc[nt][2] * acc[nt][2] + acc[nt][3] * acc[nt][3];
        }
        #pragma unroll
        for (int o = 1; o < 4; o <<= 1) {
            sum0 += __shfl_xor_sync(~0u, sum0, o);
            sq0  += __shfl_xor_sync(~0u, sq0, o);
            sum1 += __shfl_xor_sync(~0u, sum1, o);
            sq1  += __shfl_xor_sync(~0u, sq1, o);
        }
        float mu0 = sum0 * (1.0f / 128.0f);
        float iv0 = rsqrtf(sq0 * (1.0f / 128.0f) - mu0 * mu0 + 1e-5f);
        float mu1 = sum1 * (1.0f / 128.0f);
        float iv1 = rsqrtf(sq1 * (1.0f / 128.0f) - mu1 * mu1 + 1e-5f);
        float mv0 = __ldg(maskV + r0), mv1 = __ldg(maskV + r1);
        uint32_t af[32];
        #pragma unroll
        for (int nt = 0; nt < 16; ++nt) {
            int c = nt * 8 + 2 * tg;
            float gx = g2s[c], gy = g2s[c + 1], bx = b2s[c], by = b2s[c + 1];
            float2 y0 = { ((acc[nt][0] - mu0) * iv0 * gx + bx) * mv0,
                          ((acc[nt][1] - mu0) * iv0 * gy + by) * mv0 };
            float2 y1 = { ((acc[nt][2] - mu1) * iv1 * gx + bx) * mv1,
                          ((acc[nt][3] - mu1) * iv1 * gy + by) * mv1 };
            *(float2*)(outV + (size_t)r0 * 128 + c) = y0;
            *(float2*)(outV + (size_t)r1 * 128 + c) = y1;
            uint32_t p0 = pk(y0.x, y0.y), p1 = pk(y1.x, y1.y);
            *(uint32_t*)(g_hvb + (size_t)r0 * 128 + c) = p0;
            *(uint32_t*)(g_hvb + (size_t)r1 * 128 + c) = p1;
            int kt = nt >> 1, half = nt & 1;
            af[4 * kt + 2 * half]     = p0;
            af[4 * kt + 2 * half + 1] = p1;
        }
        zero16(acc);
        gemm_reg<8>(af, w11Addr, acc);
        #pragma unroll
        for (int nt = 0; nt < 16; ++nt) {
            int c = nt * 8 + 2 * tg;
            float2 bb = *(const float2*)(b11s + c);
            *(float2*)(biasC + (size_t)r0 * 128 + c) = make_float2(acc[nt][0] + bb.x, acc[nt][1] + bb.y);
            *(float2*)(biasC + (size_t)r1 * 128 + c) = make_float2(acc[nt][2] + bb.x, acc[nt][3] + bb.y);
        }
    }
}

extern "C" void kernel_launch(void* const* d_in, const int* in_sizes, int n_in,
                              void* d_out, int out_size) {
    const float* hV = (const float*)d_in[0];
    const float* hE = (const float*)d_in[1];
    const float* mV = (const float*)d_in[2];
    const int* Eidx = (const int*)d_in[3];
    const float* matt = (const float*)d_in[4];
    const float* W1 = (const float*)d_in[5],  *b1 = (const float*)d_in[6];
    const float* W2 = (const float*)d_in[7],  *b2 = (const float*)d_in[8];
    const float* W3 = (const float*)d_in[9],  *b3 = (const float*)d_in[10];
    const float* W11 = (const float*)d_in[11], *b11 = (const float*)d_in[12];
    const float* W12 = (const float*)d_in[13], *b12 = (const float*)d_in[14];
    const float* W13 = (const float*)d_in[15], *b13 = (const float*)d_in[16];
    const float* Win = (const float*)d_in[17], *bin = (const float*)d_in[18];
    const float* Wout = (const float*)d_in[19], *bout = (const float*)d_in[20];
    const float* g1 = (const float*)d_in[21], *bb1 = (const float*)d_in[22];
    const float* g2 = (const float*)d_in[23], *bb2 = (const float*)d_in[24];
    const float* g3 = (const float*)d_in[25], *bb3 = (const float*)d_in[26];
    float* outV = (float*)d_out;
    float* outE = (float*)d_out + HV_ELEMS;
    float* biasA; cudaGetSymbolAddress((void**)&biasA, g_biasA);
    float* biasC; cudaGetSymbolAddress((void**)&biasC, g_biasC);

    cudaFuncSetAttribute(kFoldT, cudaFuncAttributeMaxDynamicSharedMemorySize, SFOLD);
    cudaFuncSetAttribute(kEdge0, cudaFuncAttributeMaxDynamicSharedMemorySize, KE0_SMEM);
    cudaFuncSetAttribute(kEdge1, cudaFuncAttributeMaxDynamicSharedMemorySize, KE1_SMEM);
    cudaFuncSetAttribute(kF1, cudaFuncAttributeMaxDynamicSharedMemorySize, SF1);
    cudaFuncSetAttribute(kF2, cudaFuncAttributeMaxDynamicSharedMemorySize, SF2);

    kPrep<<<136, 256>>>(W1, W2, W3, W11, W12, W13, Win, Wout);
    kFoldT<<<128, 128, SFOLD>>>(hV, b1, biasA, 1);
    kEdge0<<<148, 512, KE0_SMEM>>>(hE, b2, b3, biasA, matt);
    kF1<<<128, 128, SF1>>>(hV, bin, g1, bb1);
    kF2<<<128, 128, SF2>>>(bout, g2, bb2, mV, outV, b11, biasC);
    kEdge1<<<148, 384, KE1_SMEM>>>(hE, b12, b13, biasC, Eidx, g3, bb3, outE);
}

// round 16
// speedup vs baseline: 1.2020x; 1.0103x over previous
#include <cuda_runtime.h>
#include <cuda_bf16.h>
#include <cstdint>

#define NODES 8192
#define H_ 128
#define K_ 48
#define EDGES (NODES * K_)
#define WTILES (EDGES / 16)
#define NTILES (NODES / 16)
#define HV_ELEMS (NODES * H_)
#define LDW 136

#define WB_W1   0
#define WB_W2   256
#define WB_W3   384
#define WB_W11  512
#define WB_W12  896
#define WB_W13  1024
#define WB_WIN  1152
#define WB_WOUT 1664
#define WB_ROWS 2176

__device__ __align__(16) float         g_v1[NODES * H_];
__device__ __align__(16) __nv_bfloat16 g_fb[NODES * 512];
__device__ __align__(16) __nv_bfloat16 g_hvb[NODES * H_];
__device__ __align__(16) float         g_dh[NODES * H_];
__device__ __align__(16) float         g_biasA[NODES * H_];
__device__ __align__(16) float         g_biasC[NODES * H_];
__device__ __align__(16) __nv_bfloat16 g_wb[WB_ROWS * LDW];

static __device__ __forceinline__ unsigned su32(const void* p) {
    return (unsigned)__cvta_generic_to_shared(p);
}
static __device__ __forceinline__ float gelu_f(float x) {
    float u = 0.7978845608028654f * (x + 0.044715f * x * x * x), t;
    asm("tanh.approx.f32 %0, %1;" : "=f"(t) : "f"(u));
    return 0.5f * x * (1.0f + t);
}
static __device__ __forceinline__ uint32_t pk(float x, float y) {
    __nv_bfloat162 h = __floats2bfloat162_rn(x, y);
    return *(uint32_t*)&h;
}
static __device__ __forceinline__ void copy_wb(int rowoff, void* dstsm, int rows,
                                               int tid, int nthr) {
    const uint4* src = (const uint4*)(g_wb + (size_t)rowoff * LDW);
    uint4* dst = (uint4*)dstsm;
    int n16 = rows * 17;
    for (int i = tid; i < n16; i += nthr) dst[i] = src[i];
}
static __device__ __forceinline__ void load_w(const float* g, __nv_bfloat16* s,
                                              int rows, int tid, int nthr) {
    int total4 = rows * 32;
    for (int i = tid; i < total4; i += nthr) {
        float4 w = ((const float4*)g)[i];
        int r = (i * 4) >> 7, c = (i * 4) & 127;
        *(__nv_bfloat162*)(s + r * LDW + c)     = __floats2bfloat162_rn(w.x, w.y);
        *(__nv_bfloat162*)(s + r * LDW + c + 2) = __floats2bfloat162_rn(w.z, w.w);
    }
}

#define MMA4(ac, a, b0, b1) \
    asm volatile("mma.sync.aligned.m16n8k16.row.col.f32.bf16.bf16.f32 " \
                 "{%0,%1,%2,%3},{%4,%5,%6,%7},{%8,%9},{%0,%1,%2,%3};" \
                 : "+f"((ac)[0]), "+f"((ac)[1]), "+f"((ac)[2]), "+f"((ac)[3]) \
                 : "r"((a)[0]), "r"((a)[1]), "r"((a)[2]), "r"((a)[3]), \
                   "r"(b0), "r"(b1))

static __device__ __forceinline__ void zero16(float acc[16][4]) {
    #pragma unroll
    for (int i = 0; i < 16; ++i)
        #pragma unroll
        for (int j = 0; j < 4; ++j) acc[i][j] = 0.0f;
}

template <int NKT>
static __device__ __forceinline__ void gemm_reg(const uint32_t* af, uint32_t wAddr,
                                                float acc[16][4]) {
    #pragma unroll
    for (int kt = 0; kt < NKT; ++kt) {
        #pragma unroll
        for (int nb = 0; nb < 8; ++nb) {
            uint32_t b[4];
            asm volatile("ldmatrix.sync.aligned.m8n8.x4.trans.shared.b16 {%0,%1,%2,%3},[%4];"
                         : "=r"(b[0]), "=r"(b[1]), "=r"(b[2]), "=r"(b[3])
                         : "r"(wAddr + kt * 4352 + nb * 32));
            MMA4(acc[2 * nb],     af + 4 * kt, b[0], b[1]);
            MMA4(acc[2 * nb + 1], af + 4 * kt, b[2], b[3]);
        }
    }
}

static __device__ __forceinline__ void load_af_f32(const float* r0, const float* r1,
                                                   int tg, uint32_t af[32]) {
    #pragma unroll
    for (int kt = 0; kt < 8; ++kt) {
        int c = kt * 16 + 2 * tg;
        float2 v0 = *(const float2*)(r0 + c);
        float2 v1 = *(const float2*)(r1 + c);
        float2 v2 = *(const float2*)(r0 + c + 8);
        float2 v3 = *(const float2*)(r1 + c + 8);
        af[4 * kt]     = pk(v0.x, v0.y);
        af[4 * kt + 1] = pk(v1.x, v1.y);
        af[4 * kt + 2] = pk(v2.x, v2.y);
        af[4 * kt + 3] = pk(v3.x, v3.y);
    }
}
static __device__ __forceinline__ void load_af_bf16(const __nv_bfloat16* r0,
                                                    const __nv_bfloat16* r1,
                                                    int tg, uint32_t af[32]) {
    #pragma unroll
    for (int kt = 0; kt < 8; ++kt) {
        int c = kt * 16 + 2 * tg;
        af[4 * kt]     = *(const uint32_t*)(r0 + c);
        af[4 * kt + 1] = *(const uint32_t*)(r1 + c);
        af[4 * kt + 2] = *(const uint32_t*)(r0 + c + 8);
        af[4 * kt + 3] = *(const uint32_t*)(r1 + c + 8);
    }
}
static __device__ __forceinline__ void pack_gelu(const float acc[16][4],
                                                 const float* bias, int tg,
                                                 uint32_t af[32]) {
    #pragma unroll
    for (int kt = 0; kt < 8; ++kt) {
        int n0 = 2 * kt, n1 = 2 * kt + 1;
        float2 bA = *(const float2*)(bias + n0 * 8 + 2 * tg);
        float2 bB = *(const float2*)(bias + n1 * 8 + 2 * tg);
        af[4 * kt]     = pk(gelu_f(acc[n0][0] + bA.x), gelu_f(acc[n0][1] + bA.y));
        af[4 * kt + 1] = pk(gelu_f(acc[n0][2] + bA.x), gelu_f(acc[n0][3] + bA.y));
        af[4 * kt + 2] = pk(gelu_f(acc[n1][0] + bB.x), gelu_f(acc[n1][1] + bB.y));
        af[4 * kt + 3] = pk(gelu_f(acc[n1][2] + bB.x), gelu_f(acc[n1][3] + bB.y));
    }
}

// ===== kPF: blocks [0,64) fold biasA = b1 + hV@W1[:128] & zero g_dh;
//            blocks [64,200) convert all weights into g_wb (smem-ready layout) =======
#define SFOLD (34816 + 512)
__global__ void __launch_bounds__(256, 1)
kPF(const float* __restrict__ hV, const float* __restrict__ b1,
    float* __restrict__ biasA,
    const float* __restrict__ W1, const float* __restrict__ W2,
    const float* __restrict__ W3, const float* __restrict__ W11,
    const float* __restrict__ W12, const float* __restrict__ W13,
    const float* __restrict__ Win, const float* __restrict__ Wout) {
    extern __shared__ char sm[];
    int tid = threadIdx.x;
    if (blockIdx.x >= 64) {   // prep role
        int bid = blockIdx.x - 64;
        int total = WB_ROWS * 64;
        for (int i = bid * 256 + tid; i < total; i += 136 * 256) {
            int r = i >> 6, c2 = (i & 63) * 2;
            const float* s; int off;
            if (r < 256)       { s = W1;  off = r * 128; }
            else if (r < 384)  { s = W2;  off = (r - 256) * 128; }
            else if (r < 512)  { s = W3;  off = (r - 384) * 128; }
            else if (r < 896)  { s = W11; off = (r - 512) * 128; }
            else if (r < 1024) { s = W12; off = (r - 896) * 128; }
            else if (r < 1152) { s = W13; off = (r - 1024) * 128; }
            else if (r < 1664) { int l = r - 1152; s = Win; off = (l & 127) * 512 + (l >> 7) * 128; }
            else               { s = Wout; off = (r - 1664) * 128; }
            float2 v = *(const float2*)(s + off + c2);
            *(__nv_bfloat162*)(g_wb + (size_t)r * LDW + c2) = __floats2bfloat162_rn(v.x, v.y);
        }
        return;
    }
    // fold role
    float* bsm = (float*)(sm + 34816);
    int lane = tid & 31, warp = tid >> 5;
    int gid = lane >> 2, tg = lane & 3;
    load_w(W1, (__nv_bfloat16*)sm, 128, tid, 256);
    if (tid < 128) bsm[tid] = b1[tid];
    __syncthreads();
    uint32_t loff = (uint32_t)(((lane & 15) * LDW + ((lane >> 4) * 8)) * 2);
    uint32_t wAddr = su32(sm) + loff;
    int wt = blockIdx.x * 8 + warp;   // 64 blocks x 8 warps = 512 = NTILES
    int r0 = wt * 16 + gid, r1 = r0 + 8;
    uint32_t af[32];
    float acc[16][4];
    load_af_f32(hV + (size_t)r0 * 128, hV + (size_t)r1 * 128, tg, af);
    zero16(acc);
    gemm_reg<8>(af, wAddr, acc);
    #pragma unroll
    for (int nt = 0; nt < 16; ++nt) {
        int c = nt * 8 + 2 * tg;
        float2 bb = *(const float2*)(bsm + c);
        *(float2*)(biasA + (size_t)r0 * 128 + c) = make_float2(acc[nt][0] + bb.x, acc[nt][1] + bb.y);
        *(float2*)(biasA + (size_t)r1 * 128 + c) = make_float2(acc[nt][2] + bb.x, acc[nt][3] + bb.y);
        *(float2*)(g_dh + (size_t)r0 * 128 + c) = make_float2(0.f, 0.f);
        *(float2*)(g_dh + (size_t)r1 * 128 + c) = make_float2(0.f, 0.f);
    }
}

// ================= kEdge0: edge MLP1 + masked sum (512 thr, prefetch) ==========
#define KE0_SMEM (104448 + 1024)
__global__ void __launch_bounds__(512, 1)
kEdge0(const float* __restrict__ hE,
       const float* __restrict__ b2, const float* __restrict__ b3,
       const float* __restrict__ bias1, const float* __restrict__ matt) {
    extern __shared__ char sm[];
    float* bs = (float*)(sm + 104448);
    int tid = threadIdx.x, lane = tid & 31, warp = tid >> 5;
    int gid = lane >> 2, tg = lane & 3;

    copy_wb(WB_W1 + 128, sm, 384, tid, 512);
    if (tid < 128) { bs[tid] = b2[tid]; bs[128 + tid] = b3[tid]; }
    __syncthreads();
    float* b2s = bs; float* b3s = bs + 128;

    uint32_t loff = (uint32_t)(((lane & 15) * LDW + ((lane >> 4) * 8)) * 2);
    uint32_t w1Addr = su32(sm) + loff;
    uint32_t w2Addr = w1Addr + 34816;
    uint32_t w3Addr = w2Addr + 34816;

    const int stride = gridDim.x * 16;
    int wt = blockIdx.x * 16 + warp;
    uint32_t af[32];
    float acc[16][4];
    if (wt < WTILES) {
        int r0 = wt * 16 + gid;
        load_af_f32(hE + (size_t)r0 * 128, hE + (size_t)(r0 + 8) * 128, tg, af);
    }
    while (wt < WTILES) {
        int rowbase = wt * 16;
        int r0 = rowbase + gid, r1 = r0 + 8;
        int node = rowbase / 48;
        zero16(acc);
        gemm_reg<8>(af, w1Addr, acc);
        pack_gelu(acc, bias1 + (size_t)node * 128, tg, af);
        zero16(acc);
        gemm_reg<8>(af, w2Addr, acc);
        pack_gelu(acc, b2s, tg, af);
        zero16(acc);
        gemm_reg<8>(af, w3Addr, acc);

        int wtn = wt + stride;
        if (wtn < WTILES) {
            int rn = wtn * 16 + gid;
            load_af_f32(hE + (size_t)rn * 128, hE + (size_t)(rn + 8) * 128, tg, af);
        }

        float m0 = __ldg(matt + r0), m1 = __ldg(matt + r1);
        #pragma unroll
        for (int nt = 0; nt < 16; ++nt) {
            float2 b = *(const float2*)(b3s + nt * 8 + 2 * tg);
            acc[nt][0] = (acc[nt][0] + b.x) * m0 + (acc[nt][2] + b.x) * m1;
            acc[nt][1] = (acc[nt][1] + b.y) * m0 + (acc[nt][3] + b.y) * m1;
        }
        #pragma unroll
        for (int o = 4; o < 32; o <<= 1)
            #pragma unroll
            for (int nt = 0; nt < 16; ++nt) {
                acc[nt][0] += __shfl_xor_sync(~0u, acc[nt][0], o);
                acc[nt][1] += __shfl_xor_sync(~0u, acc[nt][1], o);
            }
        if (lane < 4) {
            float* dst = g_dh + (size_t)node * 128;
            #pragma unroll
            for (int nt = 0; nt < 16; ++nt) {
                atomicAdd(dst + nt * 8 + 2 * lane,     acc[nt][0]);
                atomicAdd(dst + nt * 8 + 2 * lane + 1, acc[nt][1]);
            }
        }
        wt = wtn;
    }
}

// ===== kEdge1: edge MLP2 + LN3 (384 thr, dual prefetch) =====
#define KE1_SMEM (139264 + 2048)
__global__ void __launch_bounds__(384, 1)
kEdge1(const float* __restrict__ hE,
       const float* __restrict__ b2, const float* __restrict__ b3,
       const float* __restrict__ bias1, const int* __restrict__ Eidx,
       const float* __restrict__ g3, const float* __restrict__ bb3,
       float* __restrict__ outE) {
    extern __shared__ char sm[];
    float* bs = (float*)(sm + 139264);
    int tid = threadIdx.x, lane = tid & 31, warp = tid >> 5;
    int gid = lane >> 2, tg = lane & 3;

    copy_wb(WB_W11 + 128, sm, 512, tid, 384);
    if (tid < 128) {
        bs[tid] = b2[tid]; bs[128 + tid] = b3[tid];
        bs[256 + tid] = g3[tid]; bs[384 + tid] = bb3[tid];
    }
    __syncthreads();
    float* b2s = bs; float* b3s = bs + 128; float* g3s = bs + 256; float* bb3s = bs + 384;

    uint32_t loff = (uint32_t)(((lane & 15) * LDW + ((lane >> 4) * 8)) * 2);
    uint32_t w1Addr = su32(sm) + loff;
    uint32_t w2Addr = w1Addr + 69632;
    uint32_t w3Addr = w2Addr + 34816;

    const int stride = gridDim.x * 12;
    int wt = blockIdx.x * 12 + warp;
    uint32_t afE[32], afG[32];
    float acc[16][4];
    if (wt < WTILES) {
        int rb = wt * 16, r0 = rb + gid;
        load_af_f32(hE + (size_t)r0 * 128, hE + (size_t)(r0 + 8) * 128, tg, afE);
        int bbase = (rb / 98304) * 2048;
        int n0 = bbase + __ldg(Eidx + r0), n1 = bbase + __ldg(Eidx + r0 + 8);
        load_af_bf16(g_hvb + (size_t)n0 * 128, g_hvb + (size_t)n1 * 128, tg, afG);
    }
    while (wt < WTILES) {
        int rowbase = wt * 16;
        int r0 = rowbase + gid, r1 = r0 + 8;
        int node = rowbase / 48;
        zero16(acc);
        gemm_reg<8>(afE, w1Addr, acc);
        gemm_reg<8>(afG, w1Addr + 128 * 272, acc);
        pack_gelu(acc, bias1 + (size_t)node * 128, tg, afE);

        int wtn = wt + stride;
        if (wtn < WTILES) {
            int rbn = wtn * 16, rn = rbn + gid;
            int bbn = (rbn / 98304) * 2048;
            int n0 = bbn + __ldg(Eidx + rn), n1 = bbn + __ldg(Eidx + rn + 8);
            load_af_bf16(g_hvb + (size_t)n0 * 128, g_hvb + (size_t)n1 * 128, tg, afG);
        }

        zero16(acc);
        gemm_reg<8>(afE, w2Addr, acc);
        pack_gelu(acc, b2s, tg, afE);
        zero16(acc);
        gemm_reg<8>(afE, w3Addr, acc);

        if (wtn < WTILES) {
            int rn = wtn * 16 + gid;
            load_af_f32(hE + (size_t)rn * 128, hE + (size_t)(rn + 8) * 128, tg, afE);
        }

        {
            const float* e0 = hE + (size_t)r0 * 128;
            const float* e1 = hE + (size_t)r1 * 128;
            float sum0 = 0.f, sq0 = 0.f, sum1 = 0.f, sq1 = 0.f;
            #pragma unroll
            for (int nt = 0; nt < 16; ++nt) {
                int c = nt * 8 + 2 * tg;
                float2 b  = *(const float2*)(b3s + c);
                float2 h0 = *(const float2*)(e0 + c);
                float2 h1 = *(const float2*)(e1 + c);
                acc[nt][0] += b.x + h0.x; acc[nt][1] += b.y + h0.y;
                acc[nt][2] += b.x + h1.x; acc[nt][3] += b.y + h1.y;
                sum0 += acc[nt][0] + acc[nt][1];
                sq0  += acc[nt][0] * acc[nt][0] + acc[nt][1] * acc[nt][1];
                sum1 += acc[nt][2] + acc[nt][3];
                sq1  += acc[nt][2] * acc[nt][2] + acc[nt][3] * acc[nt][3];
            }
            #pragma unroll
            for (int o = 1; o < 4; o <<= 1) {
                sum0 += __shfl_xor_sync(~0u, sum0, o);
                sq0  += __shfl_xor_sync(~0u, sq0, o);
                sum1 += __shfl_xor_sync(~0u, sum1, o);
                sq1  += __shfl_xor_sync(~0u, sq1, o);
            }
            float mu0 = sum0 * (1.0f / 128.0f);
            float iv0 = rsqrtf(sq0 * (1.0f / 128.0f) - mu0 * mu0 + 1e-5f);
            float mu1 = sum1 * (1.0f / 128.0f);
            float iv1 = rsqrtf(sq1 * (1.0f / 128.0f) - mu1 * mu1 + 1e-5f);
            float* o0 = outE + (size_t)r0 * 128;
            float* o1 = outE + (size_t)r1 * 128;
            #pragma unroll
            for (int nt = 0; nt < 16; ++nt) {
                int c = nt * 8 + 2 * tg;
                float gx = g3s[c], gy = g3s[c + 1];
                float bx = bb3s[c], by = bb3s[c + 1];
                *(float2*)(o0 + c) = make_float2((acc[nt][0] - mu0) * iv0 * gx + bx,
                                                 (acc[nt][1] - mu0) * iv0 * gy + by);
                *(float2*)(o1 + c) = make_float2((acc[nt][2] - mu1) * iv1 * gx + bx,
                                                 (acc[nt][3] - mu1) * iv1 * gy + by);
            }
        }
        wt = wtn;
    }
}

// ============ kF1 (fused LN1, 256 thr / 64 CTAs) =====
#define SF1 (4 * 34816 + 2048 + 1024)
__global__ void __launch_bounds__(256, 1)
kF1(const float* __restrict__ hV, const float* __restrict__ bin,
    const float* __restrict__ g1, const float* __restrict__ bb1) {
    extern __shared__ char sm[];
    float* bin_s = (float*)(sm + 4 * 34816);
    float* g1s = bin_s + 512;
    float* b1s = g1s + 128;
    int tid = threadIdx.x, lane = tid & 31, warp = tid >> 5;
    int gid = lane >> 2, tg = lane & 3;
    copy_wb(WB_WIN, sm, 512, tid, 256);
    for (int i = tid; i < 512; i += 256) bin_s[i] = bin[i];
    if (tid < 128) { g1s[tid] = g1[tid]; b1s[tid] = bb1[tid]; }
    __syncthreads();
    uint32_t loff = (uint32_t)(((lane & 15) * LDW + ((lane >> 4) * 8)) * 2);

    for (int wt = blockIdx.x * 8 + warp; wt < NTILES; wt += gridDim.x * 8) {
        int r0 = wt * 16 + gid, r1 = r0 + 8;
        const float* hv0 = hV + (size_t)r0 * 128;
        const float* hv1 = hV + (size_t)r1 * 128;
        const float* dh0 = g_dh + (size_t)r0 * 128;
        const float* dh1 = g_dh + (size_t)r1 * 128;
        float x0[32], x1[32];
        float sum0 = 0.f, sq0 = 0.f, sum1 = 0.f, sq1 = 0.f;
        #pragma unroll
        for (int j = 0; j < 16; ++j) {
            int c = (j >> 1) * 16 + (j & 1) * 8 + 2 * tg;
            float2 a0 = *(const float2*)(hv0 + c);
            float2 d0 = *(const float2*)(dh0 + c);
            float2 a1 = *(const float2*)(hv1 + c);
            float2 d1 = *(const float2*)(dh1 + c);
            x0[2 * j]     = a0.x + d0.x * (1.0f / 30.0f);
            x0[2 * j + 1] = a0.y + d0.y * (1.0f / 30.0f);
            x1[2 * j]     = a1.x + d1.x * (1.0f / 30.0f);
            x1[2 * j + 1] = a1.y + d1.y * (1.0f / 30.0f);
            sum0 += x0[2 * j] + x0[2 * j + 1];
            sq0  += x0[2 * j] * x0[2 * j] + x0[2 * j + 1] * x0[2 * j + 1];
            sum1 += x1[2 * j] + x1[2 * j + 1];
            sq1  += x1[2 * j] * x1[2 * j] + x1[2 * j + 1] * x1[2 * j + 1];
        }
        #pragma unroll
        for (int o = 1; o < 4; o <<= 1) {
            sum0 += __shfl_xor_sync(~0u, sum0, o);
            sq0  += __shfl_xor_sync(~0u, sq0, o);
            sum1 += __shfl_xor_sync(~0u, sum1, o);
            sq1  += __shfl_xor_sync(~0u, sq1, o);
        }
        float mu0 = sum0 * (1.0f / 128.0f);
        float iv0 = rsqrtf(sq0 * (1.0f / 128.0f) - mu0 * mu0 + 1e-5f);
        float mu1 = sum1 * (1.0f / 128.0f);
        float iv1 = rsqrtf(sq1 * (1.0f / 128.0f) - mu1 * mu1 + 1e-5f);
        uint32_t af[32];
        #pragma unroll
        for (int j = 0; j < 16; ++j) {
            int c = (j >> 1) * 16 + (j & 1) * 8 + 2 * tg;
            float y0a = (x0[2 * j] - mu0) * iv0 * g1s[c] + b1s[c];
            float y0b = (x0[2 * j + 1] - mu0) * iv0 * g1s[c + 1] + b1s[c + 1];
            float y1a = (x1[2 * j] - mu1) * iv1 * g1s[c] + b1s[c];
            float y1b = (x1[2 * j + 1] - mu1) * iv1 * g1s[c + 1] + b1s[c + 1];
            *(float2*)(g_v1 + (size_t)r0 * 128 + c) = make_float2(y0a, y0b);
            *(float2*)(g_v1 + (size_t)r1 * 128 + c) = make_float2(y1a, y1b);
            int kt = j >> 1, half = j & 1;
            af[4 * kt + 2 * half]     = pk(y0a, y0b);
            af[4 * kt + 2 * half + 1] = pk(y1a, y1b);
        }
        float acc[16][4];
        #pragma unroll
        for (int ng = 0; ng < 4; ++ng) {
            zero16(acc);
            gemm_reg<8>(af, su32(sm + ng * 34816) + loff, acc);
            #pragma unroll
            for (int nt = 0; nt < 16; ++nt) {
                int cg = ng * 128 + nt * 8 + 2 * tg;
                float2 b = *(const float2*)(bin_s + cg);
                *(uint32_t*)(g_fb + (size_t)r0 * 512 + cg) =
                    pk(gelu_f(acc[nt][0] + b.x), gelu_f(acc[nt][1] + b.y));
                *(uint32_t*)(g_fb + (size_t)r1 * 512 + cg) =
                    pk(gelu_f(acc[nt][2] + b.x), gelu_f(acc[nt][3] + b.y));
            }
        }
    }
}

// ==== kF2 (fused fold, 256 thr / 64 CTAs) ==
#define SF2 (139264 + 34816 + 2048)
__global__ void __launch_bounds__(256, 1)
kF2(const float* __restrict__ bout, const float* __restrict__ g2,
    const float* __restrict__ bb2, const float* __restrict__ maskV,
    float* __restrict__ outV, const float* __restrict__ b11,
    float* __restrict__ biasC) {
    extern __shared__ char sm[];
    float* bs = (float*)(sm + 139264 + 34816);
    int tid = threadIdx.x, lane = tid & 31, warp = tid >> 5;
    int gid = lane >> 2, tg = lane & 3;
    copy_wb(WB_WOUT, sm, 512, tid, 256);
    copy_wb(WB_W11, sm + 139264, 128, tid, 256);
    if (tid < 128) { bs[tid] = bout[tid]; bs[128 + tid] = g2[tid];
                     bs[256 + tid] = bb2[tid]; bs[384 + tid] = b11[tid]; }
    __syncthreads();
    float* bo = bs; float* g2s = bs + 128; float* b2s = bs + 256; float* b11s = bs + 384;
    uint32_t loff = (uint32_t)(((lane & 15) * LDW + ((lane >> 4) * 8)) * 2);
    uint32_t wAddr = su32(sm) + loff;
    uint32_t w11Addr = wAddr + 139264;

    for (int wt = blockIdx.x * 8 + warp; wt < NTILES; wt += gridDim.x * 8) {
        int r0 = wt * 16 + gid, r1 = r0 + 8;
        const __nv_bfloat16* f0 = g_fb + (size_t)r0 * 512;
        const __nv_bfloat16* f1 = g_fb + (size_t)r1 * 512;
        float acc[16][4];
        zero16(acc);
        #pragma unroll 4
        for (int kt = 0; kt < 32; ++kt) {
            uint32_t a[4];
            int c = kt * 16 + 2 * tg;
            a[0] = *(const uint32_t*)(f0 + c);
            a[1] = *(const uint32_t*)(f1 + c);
            a[2] = *(const uint32_t*)(f0 + c + 8);
            a[3] = *(const uint32_t*)(f1 + c + 8);
            #pragma unroll
            for (int nb = 0; nb < 8; ++nb) {
                uint32_t b[4];
                asm volatile("ldmatrix.sync.aligned.m8n8.x4.trans.shared.b16 {%0,%1,%2,%3},[%4];"
                             : "=r"(b[0]), "=r"(b[1]), "=r"(b[2]), "=r"(b[3])
                             : "r"(wAddr + kt * 4352 + nb * 32));
                MMA4(acc[2 * nb],     a, b[0], b[1]);
                MMA4(acc[2 * nb + 1], a, b[2], b[3]);
            }
        }
        const float* v0 = g_v1 + (size_t)r0 * 128;
        const float* v1 = g_v1 + (size_t)r1 * 128;
        float sum0 = 0.f, sq0 = 0.f, sum1 = 0.f, sq1 = 0.f;
        #pragma unroll
        for (int nt = 0; nt < 16; ++nt) {
            int c = nt * 8 + 2 * tg;
            float2 b  = *(const float2*)(bo + c);
            float2 h0 = *(const float2*)(v0 + c);
            float2 h1 = *(const float2*)(v1 + c);
            acc[nt][0] += b.x + h0.x; acc[nt][1] += b.y + h0.y;
            acc[nt][2] += b.x + h1.x; acc[nt][3] += b.y + h1.y;
            sum0 += acc[nt][0] + acc[nt][1];
            sq0  += acc[nt][0] * acc[nt][0] + acc[nt][1] * acc[nt][1];
            sum1 += acc[nt][2] + acc[nt][3];
            sq1  += acc[nt][2] * acc[nt][2] + acc[nt][3] * acc[nt][3];
        }
        #pragma unroll
        for (int o = 1; o < 4; o <<= 1) {
            sum0 += __shfl_xor_sync(~0u, sum0, o);
            sq0  += __shfl_xor_sync(~0u, sq0, o);
            sum1 += __shfl_xor_sync(~0u, sum1, o);
            sq1  += __shfl_xor_sync(~0u, sq1, o);
        }
        float mu0 = sum0 * (1.0f / 128.0f);
        float iv0 = rsqrtf(sq0 * (1.0f / 128.0f) - mu0 * mu0 + 1e-5f);
        float mu1 = sum1 * (1.0f / 128.0f);
        float iv1 = rsqrtf(sq1 * (1.0f / 128.0f) - mu1 * mu1 + 1e-5f);
        float mv0 = __ldg(maskV + r0), mv1 = __ldg(maskV + r1);
        uint32_t af[32];
        #pragma unroll
        for (int nt = 0; nt < 16; ++nt) {
            int c = nt * 8 + 2 * tg;
            float gx = g2s[c], gy = g2s[c + 1], bx = b2s[c], by = b2s[c + 1];
            float2 y0 = { ((acc[nt][0] - mu0) * iv0 * gx + bx) * mv0,
                          ((acc[nt][1] - mu0) * iv0 * gy + by) * mv0 };
            float2 y1 = { ((acc[nt][2] - mu1) * iv1 * gx + bx) * mv1,
                          ((acc[nt][3] - mu1) * iv1 * gy + by) * mv1 };
            *(float2*)(outV + (size_t)r0 * 128 + c) = y0;
            *(float2*)(outV + (size_t)r1 * 128 + c) = y1;
            uint32_t p0 = pk(y0.x, y0.y), p1 = pk(y1.x, y1.y);
            *(uint32_t*)(g_hvb + (size_t)r0 * 128 + c) = p0;
            *(uint32_t*)(g_hvb + (size_t)r1 * 128 + c) = p1;
            int kt = nt >> 1, half = nt & 1;
            af[4 * kt + 2 * half]     = p0;
            af[4 * kt + 2 * half + 1] = p1;
        }
        zero16(acc);
        gemm_reg<8>(af, w11Addr, acc);
        #pragma unroll
        for (int nt = 0; nt < 16; ++nt) {
            int c = nt * 8 + 2 * tg;
            float2 bb = *(const float2*)(b11s + c);
            *(float2*)(biasC + (size_t)r0 * 128 + c) = make_float2(acc[nt][0] + bb.x, acc[nt][1] + bb.y);
            *(float2*)(biasC + (size_t)r1 * 128 + c) = make_float2(acc[nt][2] + bb.x, acc[nt][3] + bb.y);
        }
    }
}

extern "C" void kernel_launch(void* const* d_in, const int* in_sizes, int n_in,
                              void* d_out, int out_size) {
    const float* hV = (const float*)d_in[0];
    const float* hE = (const float*)d_in[1];
    const float* mV = (const float*)d_in[2];
    const int* Eidx = (const int*)d_in[3];
    const float* matt = (const float*)d_in[4];
    const float* W1 = (const float*)d_in[5],  *b1 = (const float*)d_in[6];
    const float* W2 = (const float*)d_in[7],  *b2 = (const float*)d_in[8];
    const float* W3 = (const float*)d_in[9],  *b3 = (const float*)d_in[10];
    const float* W11 = (const float*)d_in[11], *b11 = (const float*)d_in[12];
    const float* W12 = (const float*)d_in[13], *b12 = (const float*)d_in[14];
    const float* W13 = (const float*)d_in[15], *b13 = (const float*)d_in[16];
    const float* Win = (const float*)d_in[17], *bin = (const float*)d_in[18];
    const float* Wout = (const float*)d_in[19], *bout = (const float*)d_in[20];
    const float* g1 = (const float*)d_in[21], *bb1 = (const float*)d_in[22];
    const float* g2 = (const float*)d_in[23], *bb2 = (const float*)d_in[24];
    const float* g3 = (const float*)d_in[25], *bb3 = (const float*)d_in[26];
    float* outV = (float*)d_out;
    float* outE = (float*)d_out + HV_ELEMS;
    float* biasA; cudaGetSymbolAddress((void**)&biasA, g_biasA);
    float* biasC; cudaGetSymbolAddress((void**)&biasC, g_biasC);

    cudaFuncSetAttribute(kPF, cudaFuncAttributeMaxDynamicSharedMemorySize, SFOLD);
    cudaFuncSetAttribute(kEdge0, cudaFuncAttributeMaxDynamicSharedMemorySize, KE0_SMEM);
    cudaFuncSetAttribute(kEdge1, cudaFuncAttributeMaxDynamicSharedMemorySize, KE1_SMEM);
    cudaFuncSetAttribute(kF1, cudaFuncAttributeMaxDynamicSharedMemorySize, SF1);
    cudaFuncSetAttribute(kF2, cudaFuncAttributeMaxDynamicSharedMemorySize, SF2);

    kPF<<<200, 256, SFOLD>>>(hV, b1, biasA, W1, W2, W3, W11, W12, W13, Win, Wout);
    kEdge0<<<148, 512, KE0_SMEM>>>(hE, b2, b3, biasA, matt);
    kF1<<<64, 256, SF1>>>(hV, bin, g1, bb1);
    kF2<<<64, 256, SF2>>>(bout, g2, bb2, mV, outV, b11, biasC);
    kEdge1<<<148, 384, KE1_SMEM>>>(hE, b12, b13, biasC, Eidx, g3, bb3, outE);
}